// round 11
// baseline (speedup 1.0000x reference)
#include <cuda_runtime.h>
#include <cuda_bf16.h>
#include <cstdint>

// ===========================================================================
// GCN auto-encoder.
//  - GEMMs: mma.sync m16n8k16 bf16 (HMMA), bf16x3 split (hi*hi+hi*lo+lo*hi,
//    fp32 accum) ~ fp32 accuracy. cp.async 2-stage pipeline + ldmatrix frags.
//    BM=128, BN=64, 256 threads (empirically optimal shape).
//  - Aggregation: per-launch CSR, warp-per-node gather-reduce (vectorized,
//    unroll-8 MLP), fused bias/relu/bf16-split epilogue. No float atomics.
//  - CSR build + bias combines overlapped on a forked stream (kept shorter
//    than the main pre-join segment).
// ===========================================================================

constexpr int MAXN = 50000;
constexpr int MAXE = 800000;

__device__ __align__(256) float g_dinv[MAXN];
__device__ __align__(256) int   g_degi[MAXN];
__device__ __align__(256) int   g_off[MAXN + 1];
__device__ __align__(256) int   g_cur[MAXN];
__device__ __align__(256) int   g_srcs[MAXE];
__device__ __align__(256) float g_bufA[(size_t)MAXN * 128];
__device__ __align__(256) float g_cbias[2048];
__device__ __align__(256) __nv_bfloat16 g_Ahi[(size_t)MAXN * 256];
__device__ __align__(256) __nv_bfloat16 g_Alo[(size_t)MAXN * 256];
__device__ __align__(256) __nv_bfloat16 g_Bhi[(size_t)MAXN * 256];
__device__ __align__(256) __nv_bfloat16 g_Blo[(size_t)MAXN * 256];
__device__ __align__(256) __nv_bfloat16 g_Whi[262144];
__device__ __align__(256) __nv_bfloat16 g_Wlo[262144];

// ------------------------------- helpers -----------------------------------

__device__ __forceinline__ uint32_t smem_u32(const void* p) {
    uint32_t a;
    asm("{ .reg .u64 t; cvta.to.shared.u64 t, %1; cvt.u32.u64 %0, t; }"
        : "=r"(a) : "l"(p));
    return a;
}

__device__ __forceinline__ void cp16(uint32_t dst, const void* src, bool pred) {
    asm volatile("cp.async.cg.shared.global [%0], [%1], 16, %2;"
                 :: "r"(dst), "l"(src), "r"(pred ? 16 : 0));
}
__device__ __forceinline__ void cp_commit() {
    asm volatile("cp.async.commit_group;");
}
__device__ __forceinline__ void cp_wait1() {
    asm volatile("cp.async.wait_group 1;");
}

__device__ __forceinline__ void ldm_x4(uint32_t r[4], uint32_t addr) {
    asm volatile("ldmatrix.sync.aligned.m8n8.x4.shared.b16 {%0,%1,%2,%3}, [%4];"
                 : "=r"(r[0]), "=r"(r[1]), "=r"(r[2]), "=r"(r[3]) : "r"(addr));
}

__device__ __forceinline__ void mma16816(float c[4], const uint32_t a[4],
                                         const uint32_t b0, const uint32_t b1) {
    asm volatile(
        "mma.sync.aligned.m16n8k16.row.col.f32.bf16.bf16.f32 "
        "{%0,%1,%2,%3}, {%4,%5,%6,%7}, {%8,%9}, {%0,%1,%2,%3};"
        : "+f"(c[0]), "+f"(c[1]), "+f"(c[2]), "+f"(c[3])
        : "r"(a[0]), "r"(a[1]), "r"(a[2]), "r"(a[3]), "r"(b0), "r"(b1));
}

// ------------------------------- tensor GEMM -------------------------------
// C[M,N] = A[M,K] @ W,  W pre-transposed+split to [N,K] bf16 hi/lo.
// BM=128, BN=64, BK=32, 256 threads (8 warps, 4Mx2N), 2-stage cp.async,
// ldmatrix fragment loads.

template <int K, bool BIAS, bool RELU, bool SPLITOUT>
__global__ void __launch_bounds__(256)
mm_k(const __nv_bfloat16* __restrict__ Ahi, const __nv_bfloat16* __restrict__ Alo,
     const __nv_bfloat16* __restrict__ Bhi, const __nv_bfloat16* __restrict__ Blo,
     const float* __restrict__ bias, float* __restrict__ Cf,
     __nv_bfloat16* __restrict__ Chi, __nv_bfloat16* __restrict__ Clo,
     int M, int N) {
    constexpr int BM = 128, BK = 32, PITCH = 40;  // 80B rows, conflict-free
    constexpr int KT = K / BK;
    extern __shared__ __nv_bfloat16 smem[];
    const uint32_t sbase = smem_u32(smem);

    const int tid = threadIdx.x;
    const int lane = tid & 31, wid = tid >> 5;
    const int wm = wid & 3, wn = wid >> 2;
    const int bm = blockIdx.y * BM, bn = blockIdx.x * 64;

    float acc[2][4][4];
#pragma unroll
    for (int i = 0; i < 2; i++)
#pragma unroll
        for (int j = 0; j < 4; j++)
#pragma unroll
            for (int l = 0; l < 4; l++) acc[i][j][l] = 0.f;

    auto load_stage = [&](int st, int k0) {
#pragma unroll
        for (int l = 0; l < 4; l++) {  // A: 1024 16B chunks
            int idx = tid + l * 256;
            int mat = idx >> 9, rem = idx & 511, row = rem >> 2, q = rem & 3;
            int g = bm + row;
            const __nv_bfloat16* src =
                (mat ? Alo : Ahi) + (size_t)g * K + k0 + q * 8;
            uint32_t dst = sbase + (uint32_t)((((st * 2 + mat) * 128 + row) * PITCH + q * 8) * 2);
            cp16(dst, src, g < M);
        }
#pragma unroll
        for (int l = 0; l < 2; l++) {  // B: 512 16B chunks
            int idx = tid + l * 256;
            int mat = idx >> 8, rem = idx & 255, row = rem >> 2, q = rem & 3;
            const __nv_bfloat16* src =
                (mat ? Blo : Bhi) + (size_t)(bn + row) * K + k0 + q * 8;
            uint32_t dst = sbase + (uint32_t)(((512 + (st * 2 + mat) * 64 + row) * PITCH + q * 8) * 2);
            cp16(dst, src, true);
        }
    };

    // per-lane ldmatrix address components (element offsets; x2 for bytes)
    const int aRow = lane & 15, aCol = (lane >> 4) * 8;
    const int bRow = ((lane >> 4) & 1) * 8 + (lane & 7);
    const int bCol = ((lane >> 3) & 1) * 8;

    load_stage(0, 0);
    cp_commit();

    for (int kt = 0; kt < KT; kt++) {
        if (kt + 1 < KT) load_stage((kt + 1) & 1, (kt + 1) * BK);
        cp_commit();
        cp_wait1();
        __syncthreads();

        const int st = kt & 1;
        const uint32_t aOff0 = (uint32_t)((st * 2) * 128 * PITCH);
        const uint32_t aOff1 = (uint32_t)((st * 2 + 1) * 128 * PITCH);
        const uint32_t bOff0 = (uint32_t)((512 + (st * 2) * 64) * PITCH);
        const uint32_t bOff1 = (uint32_t)((512 + (st * 2 + 1) * 64) * PITCH);

#pragma unroll
        for (int p = 0; p < 3; p++) {
            const uint32_t aOff = (p == 2) ? aOff1 : aOff0;
            const uint32_t bOff = (p == 1) ? bOff1 : bOff0;
#pragma unroll
            for (int ks = 0; ks < 2; ks++) {
                const int kb = ks * 16;
                uint32_t af[2][4], bf[2][4];
#pragma unroll
                for (int mt = 0; mt < 2; mt++) {
                    int R = wm * 32 + mt * 16;
                    uint32_t addr = sbase +
                        (aOff + (uint32_t)((R + aRow) * PITCH + kb + aCol)) * 2;
                    ldm_x4(af[mt], addr);
                }
#pragma unroll
                for (int pr = 0; pr < 2; pr++) {
                    int R = wn * 32 + pr * 16;
                    uint32_t addr = sbase +
                        (bOff + (uint32_t)((R + bRow) * PITCH + kb + bCol)) * 2;
                    ldm_x4(bf[pr], addr);
                }
#pragma unroll
                for (int mt = 0; mt < 2; mt++)
#pragma unroll
                    for (int nt = 0; nt < 4; nt++)
                        mma16816(acc[mt][nt], af[mt],
                                 bf[nt >> 1][(nt & 1) * 2], bf[nt >> 1][(nt & 1) * 2 + 1]);
            }
        }
        __syncthreads();
    }

    // epilogue
#pragma unroll
    for (int mt = 0; mt < 2; mt++) {
        int r0 = bm + wm * 32 + mt * 16 + (lane >> 2);
#pragma unroll
        for (int nt = 0; nt < 4; nt++) {
            int col = bn + wn * 32 + nt * 8 + (lane & 3) * 2;
            float b0 = 0.f, b1 = 0.f;
            if (BIAS) { b0 = __ldg(&bias[col]); b1 = __ldg(&bias[col + 1]); }
#pragma unroll
            for (int hh = 0; hh < 2; hh++) {
                int r = r0 + hh * 8;
                if (r < M) {
                    float v0 = acc[mt][nt][hh * 2 + 0] + b0;
                    float v1 = acc[mt][nt][hh * 2 + 1] + b1;
                    if (RELU) { v0 = fmaxf(v0, 0.f); v1 = fmaxf(v1, 0.f); }
                    if (SPLITOUT) {
                        __nv_bfloat16 h0 = __float2bfloat16(v0);
                        __nv_bfloat16 h1 = __float2bfloat16(v1);
                        __nv_bfloat162 hv = {h0, h1};
                        __nv_bfloat162 lv = {
                            __float2bfloat16(v0 - __bfloat162float(h0)),
                            __float2bfloat16(v1 - __bfloat162float(h1))};
                        *(__nv_bfloat162*)(Chi + (size_t)r * N + col) = hv;
                        *(__nv_bfloat162*)(Clo + (size_t)r * N + col) = lv;
                    } else {
                        *(float2*)(Cf + (size_t)r * N + col) = make_float2(v0, v1);
                    }
                }
            }
        }
    }
}

// ------------------------------ CSR building -------------------------------

__global__ void deg_count_k(const int* __restrict__ dst, int* d, int E) {
    int e = blockIdx.x * blockDim.x + threadIdx.x;
    if (e < E) atomicAdd(&d[dst[e]], 1);
}

// exclusive scan over degrees -> offsets + cursor copy + dinv
__global__ void scan_k(const int* __restrict__ deg, int* __restrict__ off,
                       int* __restrict__ cur, float* __restrict__ dinv, int n) {
    __shared__ int part[1024];
    int t = threadIdx.x;
    int per = (n + 1023) >> 10;
    int lo = t * per;
    int hi = min(lo + per, n);
    int s = 0;
    for (int i = lo; i < hi; i++) s += deg[i];
    part[t] = s;
    __syncthreads();
    for (int d = 1; d < 1024; d <<= 1) {
        int v = (t >= d) ? part[t - d] : 0;
        __syncthreads();
        part[t] += v;
        __syncthreads();
    }
    int run = (t == 0) ? 0 : part[t - 1];
    for (int i = lo; i < hi; i++) {
        off[i] = run;
        cur[i] = run;
        dinv[i] = rsqrtf((float)(deg[i] + 1));
        run += deg[i];
    }
    if (t == 1023) off[n] = part[1023];
}

__global__ void fill_k(const int* __restrict__ src, const int* __restrict__ dst,
                       int* cur, int* __restrict__ srcs, int E) {
    int e = blockIdx.x * blockDim.x + threadIdx.x;
    if (e < E) {
        int p = atomicAdd(&cur[dst[e]], 1);
        srcs[p] = src[e];
    }
}

// ------------------------------ aggregation --------------------------------
// Warp per node; lane owns V = C/32 contiguous columns (vectorized).

template <int C, bool BIAS, bool RELU>
__global__ void __launch_bounds__(256)
agg_k(const float* __restrict__ h, const int* __restrict__ off,
      const int* __restrict__ srcs, const float* __restrict__ dinv,
      const float* __restrict__ bias,
      __nv_bfloat16* __restrict__ Hi, __nv_bfloat16* __restrict__ Lo, int n) {
    constexpr int V = C / 32;
    int node = blockIdx.x * 8 + (threadIdx.x >> 5);
    if (node >= n) return;
    int lane = threadIdx.x & 31;
    int c = lane * V;
    float dv = dinv[node];

    float acc[V];
    {
        if (V == 4) {
            float4 v = *(const float4*)(h + (size_t)node * C + c);
            acc[0] = dv * v.x; acc[1] = dv * v.y;
            acc[2] = dv * v.z; acc[3] = dv * v.w;
        } else {
            float2 v = *(const float2*)(h + (size_t)node * C + c);
            acc[0] = dv * v.x; acc[1] = dv * v.y;
        }
    }

    const int b = off[node], e = off[node + 1];
    int i0 = b;
    for (; i0 + 32 <= e; i0 += 32) {
        int s = __ldg(&srcs[i0 + lane]);
        float nd = __ldg(&dinv[s]);
#pragma unroll 8
        for (int j = 0; j < 32; j++) {
            int ss = __shfl_sync(0xffffffffu, s, j);
            float nn = __shfl_sync(0xffffffffu, nd, j);
            const float* p = h + (size_t)ss * C + c;
            if (V == 4) {
                float4 v = *(const float4*)p;
                acc[0] = fmaf(nn, v.x, acc[0]);
                acc[1] = fmaf(nn, v.y, acc[1]);
                acc[2] = fmaf(nn, v.z, acc[2]);
                acc[3] = fmaf(nn, v.w, acc[3]);
            } else {
                float2 v = *(const float2*)p;
                acc[0] = fmaf(nn, v.x, acc[0]);
                acc[1] = fmaf(nn, v.y, acc[1]);
            }
        }
    }
    if (i0 < e) {
        int idx = i0 + lane;
        int s = 0;
        float nd = 0.f;
        if (idx < e) {
            s = __ldg(&srcs[idx]);
            nd = __ldg(&dinv[s]);
        }
        int cnt = e - i0;
#pragma unroll 4
        for (int j = 0; j < cnt; j++) {
            int ss = __shfl_sync(0xffffffffu, s, j);
            float nn = __shfl_sync(0xffffffffu, nd, j);
            const float* p = h + (size_t)ss * C + c;
            if (V == 4) {
                float4 v = *(const float4*)p;
                acc[0] = fmaf(nn, v.x, acc[0]);
                acc[1] = fmaf(nn, v.y, acc[1]);
                acc[2] = fmaf(nn, v.z, acc[2]);
                acc[3] = fmaf(nn, v.w, acc[3]);
            } else {
                float2 v = *(const float2*)p;
                acc[0] = fmaf(nn, v.x, acc[0]);
                acc[1] = fmaf(nn, v.y, acc[1]);
            }
        }
    }

#pragma unroll
    for (int k = 0; k < V; k++) {
        acc[k] *= dv;
        if (BIAS) acc[k] += __ldg(&bias[c + k]);
        if (RELU) acc[k] = fmaxf(acc[k], 0.f);
    }
#pragma unroll
    for (int k = 0; k < V; k += 2) {
        __nv_bfloat16 h0 = __float2bfloat16(acc[k]);
        __nv_bfloat16 h1 = __float2bfloat16(acc[k + 1]);
        __nv_bfloat162 hv = {h0, h1};
        __nv_bfloat162 lv = {__float2bfloat16(acc[k] - __bfloat162float(h0)),
                             __float2bfloat16(acc[k + 1] - __bfloat162float(h1))};
        *(__nv_bfloat162*)(Hi + (size_t)node * C + c + k) = hv;
        *(__nv_bfloat162*)(Lo + (size_t)node * C + c + k) = lv;
    }
}

// ------------------------------ split / misc -------------------------------

__global__ void asplit_k(const float* __restrict__ A, __nv_bfloat16* __restrict__ hi,
                         __nv_bfloat16* __restrict__ lo, long total4) {
    long t = (long)blockIdx.x * blockDim.x + threadIdx.x;
    if (t >= total4) return;
    float4 v = *(const float4*)(A + t * 4);
    __nv_bfloat16 h0 = __float2bfloat16(v.x), h1 = __float2bfloat16(v.y);
    __nv_bfloat16 h2 = __float2bfloat16(v.z), h3 = __float2bfloat16(v.w);
    __nv_bfloat162 H0 = {h0, h1}, H1 = {h2, h3};
    __nv_bfloat162 L0 = {__float2bfloat16(v.x - __bfloat162float(h0)),
                         __float2bfloat16(v.y - __bfloat162float(h1))};
    __nv_bfloat162 L1 = {__float2bfloat16(v.z - __bfloat162float(h2)),
                         __float2bfloat16(v.w - __bfloat162float(h3))};
    *(__nv_bfloat162*)(hi + t * 4) = H0;
    *(__nv_bfloat162*)(hi + t * 4 + 2) = H1;
    *(__nv_bfloat162*)(lo + t * 4) = L0;
    *(__nv_bfloat162*)(lo + t * 4 + 2) = L1;
}

// all 6 weight transposes+splits in one launch
struct WJobs {
    const float* W[6];
    int K[6], N[6], off[6], elems[6];
};

__global__ void wsplit_all_k(WJobs P, __nv_bfloat16* __restrict__ hi,
                             __nv_bfloat16* __restrict__ lo) {
    int i = blockIdx.x * blockDim.x + threadIdx.x;
#pragma unroll
    for (int j = 0; j < 6; j++) {
        if (i < P.elems[j]) {
            int K = P.K[j], N = P.N[j];
            int n = i / K, k = i % K;
            float v = P.W[j][(long)k * N + n];
            __nv_bfloat16 h = __float2bfloat16(v);
            hi[P.off[j] + i] = h;
            lo[P.off[j] + i] = __float2bfloat16(v - __bfloat162float(h));
            return;
        }
        i -= P.elems[j];
    }
}

// both combined biases in one launch:
//  j in [0,64):    cb[j]      = eb2@eWf + ebf
//  j in [64,1088): cb2[j-64]  = db2@dWf + dbf
__global__ void combine_bias2_k(const float* __restrict__ eb2, const float* __restrict__ eWf,
                                const float* __restrict__ ebf, const float* __restrict__ db2,
                                const float* __restrict__ dWf, const float* __restrict__ dbf,
                                float* __restrict__ cb, float* __restrict__ cb2) {
    int j = blockIdx.x * blockDim.x + threadIdx.x;
    if (j < 64) {
        float s = ebf[j];
        for (int k = 0; k < 64; k++) s += eb2[k] * eWf[k * 64 + j];
        cb[j] = s;
    } else if (j < 64 + 1024) {
        int jj = j - 64;
        float s = dbf[jj];
        for (int k = 0; k < 128; k++) s += db2[k] * dWf[k * 1024 + jj];
        cb2[jj] = s;
    }
}

// --------------------------------- launch ----------------------------------

static inline int cdiv(long a, long b) { return (int)((a + b - 1) / b); }

constexpr int MM_SMEM = (2 * 2 * 128 * 40 + 2 * 2 * 64 * 40) * 2;  // 61440B

template <int K, bool BIAS, bool RELU, bool SPLITOUT>
static void run_mm(const __nv_bfloat16* Ahi, const __nv_bfloat16* Alo,
                   const __nv_bfloat16* Bhi, const __nv_bfloat16* Blo,
                   const float* bias, float* Cf, __nv_bfloat16* Chi,
                   __nv_bfloat16* Clo, int M, int N) {
    cudaFuncSetAttribute(mm_k<K, BIAS, RELU, SPLITOUT>,
                         cudaFuncAttributeMaxDynamicSharedMemorySize, MM_SMEM);
    dim3 g(N / 64, cdiv(M, 128));
    mm_k<K, BIAS, RELU, SPLITOUT><<<g, 256, MM_SMEM>>>(
        Ahi, Alo, Bhi, Blo, bias, Cf, Chi, Clo, M, N);
}

extern "C" void kernel_launch(void* const* d_in, const int* in_sizes, int n_in,
                              void* d_out, int out_size) {
    const float* x   = (const float*)d_in[0];
    const int*   ei  = (const int*)d_in[1];
    const float* eW1 = (const float*)d_in[2];
    const float* eb1 = (const float*)d_in[3];
    const float* eW2 = (const float*)d_in[4];
    const float* eb2 = (const float*)d_in[5];
    const float* eWf = (const float*)d_in[6];
    const float* ebf = (const float*)d_in[7];
    const float* dW1 = (const float*)d_in[8];
    const float* db1 = (const float*)d_in[9];
    const float* dW2 = (const float*)d_in[10];
    const float* db2 = (const float*)d_in[11];
    const float* dWf = (const float*)d_in[12];
    const float* dbf = (const float*)d_in[13];
    float* out = (float*)d_out;

    const int M = in_sizes[0] / 128;  // 50000
    const int E = in_sizes[1] / 2;    // 800000
    const int* src = ei;
    const int* dst = ei + E;

    float *dinv, *bufA, *cbias;
    int *degi, *off, *cur, *srcs;
    __nv_bfloat16 *Ahi, *Alo, *Bh, *Bl, *Whi, *Wlo;
    cudaGetSymbolAddress((void**)&dinv, g_dinv);
    cudaGetSymbolAddress((void**)&degi, g_degi);
    cudaGetSymbolAddress((void**)&off, g_off);
    cudaGetSymbolAddress((void**)&cur, g_cur);
    cudaGetSymbolAddress((void**)&srcs, g_srcs);
    cudaGetSymbolAddress((void**)&bufA, g_bufA);
    cudaGetSymbolAddress((void**)&cbias, g_cbias);
    cudaGetSymbolAddress((void**)&Ahi, g_Ahi);
    cudaGetSymbolAddress((void**)&Alo, g_Alo);
    cudaGetSymbolAddress((void**)&Bh, g_Bhi);
    cudaGetSymbolAddress((void**)&Bl, g_Blo);
    cudaGetSymbolAddress((void**)&Whi, g_Whi);
    cudaGetSymbolAddress((void**)&Wlo, g_Wlo);

    const int O_EW1 = 0;      // 128x128
    const int O_EW2 = 16384;  // 64x128
    const int O_EWF = 24576;  // 64x64
    const int O_DW1 = 28672;  // 256x64
    const int O_DW2 = 45056;  // 128x256
    const int O_DWF = 77824;  // 1024x128

    const int T = 256;

    static cudaStream_t s2 = nullptr;
    static cudaEvent_t evFork = nullptr, evJoin = nullptr;
    if (!s2) {
        cudaStreamCreateWithFlags(&s2, cudaStreamNonBlocking);
        cudaEventCreateWithFlags(&evFork, cudaEventDisableTiming);
        cudaEventCreateWithFlags(&evJoin, cudaEventDisableTiming);
    }

    // ---- fork: CSR build + bias combines on s2 ----
    cudaEventRecord(evFork, 0);
    cudaStreamWaitEvent(s2, evFork, 0);
    cudaMemsetAsync(degi, 0, M * sizeof(int), s2);
    deg_count_k<<<cdiv(E, T), T, 0, s2>>>(dst, degi, E);
    scan_k<<<1, 1024, 0, s2>>>(degi, off, cur, dinv, M);
    fill_k<<<cdiv(E, T), T, 0, s2>>>(src, dst, cur, srcs, E);
    combine_bias2_k<<<cdiv(64 + 1024, 128), 128, 0, s2>>>(
        eb2, eWf, ebf, db2, dWf, dbf, cbias, cbias + 1024);
    cudaEventRecord(evJoin, s2);

    // ---- main stream: weight prep + first GEMM ----
    {
        WJobs P;
        const float* Ws[6] = {eW1, eW2, eWf, dW1, dW2, dWf};
        int Ks[6] = {128, 128, 64, 64, 256, 128};
        int Ns[6] = {128, 64, 64, 256, 128, 1024};
        int Os[6] = {O_EW1, O_EW2, O_EWF, O_DW1, O_DW2, O_DWF};
        int total = 0;
        for (int j = 0; j < 6; j++) {
            P.W[j] = Ws[j]; P.K[j] = Ks[j]; P.N[j] = Ns[j];
            P.off[j] = Os[j]; P.elems[j] = Ks[j] * Ns[j];
            total += P.elems[j];
        }
        wsplit_all_k<<<cdiv(total, T), T>>>(P, Whi, Wlo);
    }

    // enc GCN1 linear part: t1 = x@eW1 (independent of CSR)
    asplit_k<<<cdiv((long)M * 32, T), T>>>(x, Ahi, Alo, (long)M * 32);
    run_mm<128, false, false, false>(Ahi, Alo, Whi + O_EW1, Wlo + O_EW1,
                                     nullptr, bufA, nullptr, nullptr, M, 128);

    // ---- join: aggregation needs CSR ----
    cudaStreamWaitEvent(0, evJoin, 0);

    // h1 = relu(A(t1)+eb1) -> split Bh/Bl [M,128]
    agg_k<128, true, true><<<cdiv(M, 8), 256>>>(bufA, off, srcs, dinv, eb1, Bh, Bl, M);

    // enc GCN2: t2 = h1@eW2 ; A(t2) -> split Ahi/Alo [M,64]
    run_mm<128, false, false, false>(Bh, Bl, Whi + O_EW2, Wlo + O_EW2,
                                     nullptr, bufA, nullptr, nullptr, M, 64);
    agg_k<64, false, false><<<cdiv(M, 8), 256>>>(bufA, off, srcs, dinv, nullptr, Ahi, Alo, M);

    // z = a2@eWf + cb -> fp32 bufA [M,64]
    run_mm<64, true, false, false>(Ahi, Alo, Whi + O_EWF, Wlo + O_EWF,
                                   cbias, bufA, nullptr, nullptr, M, 64);

    // dec GCN1: A(z) -> split Bh/Bl ; h = relu(A(z)@dW1+db1) -> split Ahi/Alo [M,256]
    agg_k<64, false, false><<<cdiv(M, 8), 256>>>(bufA, off, srcs, dinv, nullptr, Bh, Bl, M);
    run_mm<64, true, true, true>(Bh, Bl, Whi + O_DW1, Wlo + O_DW1,
                                 db1, nullptr, Ahi, Alo, M, 256);

    // dec GCN2: t = h@dW2 -> fp32 ; A(t) -> split Bh/Bl [M,128]
    run_mm<256, false, false, false>(Ahi, Alo, Whi + O_DW2, Wlo + O_DW2,
                                     nullptr, bufA, nullptr, nullptr, M, 128);
    agg_k<128, false, false><<<cdiv(M, 8), 256>>>(bufA, off, srcs, dinv, nullptr, Bh, Bl, M);

    // out = a4@dWf + cb2
    run_mm<128, true, false, false>(Bh, Bl, Whi + O_DWF, Wlo + O_DWF,
                                    cbias + 1024, out, nullptr, nullptr, M, 1024);
}

// round 12
// speedup vs baseline: 1.0340x; 1.0340x over previous
#include <cuda_runtime.h>
#include <cuda_bf16.h>
#include <cstdint>

// ===========================================================================
// GCN auto-encoder.
//  - GEMMs: mma.sync m16n8k16 bf16 (HMMA), bf16x3 split (hi*hi+hi*lo+lo*hi,
//    fp32 accum) ~ fp32 accuracy. cp.async 2-stage pipeline + ldmatrix frags.
//    BM=128, BN=64, 256 threads (empirically optimal shape).
//  - Aggregation: per-launch CSR, warp-per-node gather-reduce (vectorized,
//    unroll-8), fused bias/relu/bf16-split epilogue. No float atomics.
//  - CSR build on forked stream (R8 topology); combine_bias ILP-4.
// ===========================================================================

constexpr int MAXN = 50000;
constexpr int MAXE = 800000;

__device__ __align__(256) float g_dinv[MAXN];
__device__ __align__(256) int   g_degi[MAXN];
__device__ __align__(256) int   g_off[MAXN + 1];
__device__ __align__(256) int   g_cur[MAXN];
__device__ __align__(256) int   g_srcs[MAXE];
__device__ __align__(256) float g_bufA[(size_t)MAXN * 128];
__device__ __align__(256) float g_cbias[2048];
__device__ __align__(256) __nv_bfloat16 g_Ahi[(size_t)MAXN * 256];
__device__ __align__(256) __nv_bfloat16 g_Alo[(size_t)MAXN * 256];
__device__ __align__(256) __nv_bfloat16 g_Bhi[(size_t)MAXN * 256];
__device__ __align__(256) __nv_bfloat16 g_Blo[(size_t)MAXN * 256];
__device__ __align__(256) __nv_bfloat16 g_Whi[262144];
__device__ __align__(256) __nv_bfloat16 g_Wlo[262144];

// ------------------------------- helpers -----------------------------------

__device__ __forceinline__ uint32_t smem_u32(const void* p) {
    uint32_t a;
    asm("{ .reg .u64 t; cvta.to.shared.u64 t, %1; cvt.u32.u64 %0, t; }"
        : "=r"(a) : "l"(p));
    return a;
}

__device__ __forceinline__ void cp16(uint32_t dst, const void* src, bool pred) {
    asm volatile("cp.async.cg.shared.global [%0], [%1], 16, %2;"
                 :: "r"(dst), "l"(src), "r"(pred ? 16 : 0));
}
__device__ __forceinline__ void cp_commit() {
    asm volatile("cp.async.commit_group;");
}
__device__ __forceinline__ void cp_wait1() {
    asm volatile("cp.async.wait_group 1;");
}

__device__ __forceinline__ void ldm_x4(uint32_t r[4], uint32_t addr) {
    asm volatile("ldmatrix.sync.aligned.m8n8.x4.shared.b16 {%0,%1,%2,%3}, [%4];"
                 : "=r"(r[0]), "=r"(r[1]), "=r"(r[2]), "=r"(r[3]) : "r"(addr));
}

__device__ __forceinline__ void mma16816(float c[4], const uint32_t a[4],
                                         const uint32_t b0, const uint32_t b1) {
    asm volatile(
        "mma.sync.aligned.m16n8k16.row.col.f32.bf16.bf16.f32 "
        "{%0,%1,%2,%3}, {%4,%5,%6,%7}, {%8,%9}, {%0,%1,%2,%3};"
        : "+f"(c[0]), "+f"(c[1]), "+f"(c[2]), "+f"(c[3])
        : "r"(a[0]), "r"(a[1]), "r"(a[2]), "r"(a[3]), "r"(b0), "r"(b1));
}

// ------------------------------- tensor GEMM -------------------------------
// C[M,N] = A[M,K] @ W,  W pre-transposed+split to [N,K] bf16 hi/lo.
// BM=128, BN=64, BK=32, 256 threads (8 warps, 4Mx2N), 2-stage cp.async,
// ldmatrix fragment loads.

template <int K, bool BIAS, bool RELU, bool SPLITOUT>
__global__ void __launch_bounds__(256)
mm_k(const __nv_bfloat16* __restrict__ Ahi, const __nv_bfloat16* __restrict__ Alo,
     const __nv_bfloat16* __restrict__ Bhi, const __nv_bfloat16* __restrict__ Blo,
     const float* __restrict__ bias, float* __restrict__ Cf,
     __nv_bfloat16* __restrict__ Chi, __nv_bfloat16* __restrict__ Clo,
     int M, int N) {
    constexpr int BM = 128, BK = 32, PITCH = 40;  // 80B rows, conflict-free
    constexpr int KT = K / BK;
    extern __shared__ __nv_bfloat16 smem[];
    const uint32_t sbase = smem_u32(smem);

    const int tid = threadIdx.x;
    const int lane = tid & 31, wid = tid >> 5;
    const int wm = wid & 3, wn = wid >> 2;
    const int bm = blockIdx.y * BM, bn = blockIdx.x * 64;

    float acc[2][4][4];
#pragma unroll
    for (int i = 0; i < 2; i++)
#pragma unroll
        for (int j = 0; j < 4; j++)
#pragma unroll
            for (int l = 0; l < 4; l++) acc[i][j][l] = 0.f;

    auto load_stage = [&](int st, int k0) {
#pragma unroll
        for (int l = 0; l < 4; l++) {  // A: 1024 16B chunks
            int idx = tid + l * 256;
            int mat = idx >> 9, rem = idx & 511, row = rem >> 2, q = rem & 3;
            int g = bm + row;
            const __nv_bfloat16* src =
                (mat ? Alo : Ahi) + (size_t)g * K + k0 + q * 8;
            uint32_t dst = sbase + (uint32_t)((((st * 2 + mat) * 128 + row) * PITCH + q * 8) * 2);
            cp16(dst, src, g < M);
        }
#pragma unroll
        for (int l = 0; l < 2; l++) {  // B: 512 16B chunks
            int idx = tid + l * 256;
            int mat = idx >> 8, rem = idx & 255, row = rem >> 2, q = rem & 3;
            const __nv_bfloat16* src =
                (mat ? Blo : Bhi) + (size_t)(bn + row) * K + k0 + q * 8;
            uint32_t dst = sbase + (uint32_t)(((512 + (st * 2 + mat) * 64 + row) * PITCH + q * 8) * 2);
            cp16(dst, src, true);
        }
    };

    // per-lane ldmatrix address components (element offsets; x2 for bytes)
    const int aRow = lane & 15, aCol = (lane >> 4) * 8;
    const int bRow = ((lane >> 4) & 1) * 8 + (lane & 7);
    const int bCol = ((lane >> 3) & 1) * 8;

    load_stage(0, 0);
    cp_commit();

    for (int kt = 0; kt < KT; kt++) {
        if (kt + 1 < KT) load_stage((kt + 1) & 1, (kt + 1) * BK);
        cp_commit();
        cp_wait1();
        __syncthreads();

        const int st = kt & 1;
        const uint32_t aOff0 = (uint32_t)((st * 2) * 128 * PITCH);
        const uint32_t aOff1 = (uint32_t)((st * 2 + 1) * 128 * PITCH);
        const uint32_t bOff0 = (uint32_t)((512 + (st * 2) * 64) * PITCH);
        const uint32_t bOff1 = (uint32_t)((512 + (st * 2 + 1) * 64) * PITCH);

#pragma unroll
        for (int p = 0; p < 3; p++) {
            const uint32_t aOff = (p == 2) ? aOff1 : aOff0;
            const uint32_t bOff = (p == 1) ? bOff1 : bOff0;
#pragma unroll
            for (int ks = 0; ks < 2; ks++) {
                const int kb = ks * 16;
                uint32_t af[2][4], bf[2][4];
#pragma unroll
                for (int mt = 0; mt < 2; mt++) {
                    int R = wm * 32 + mt * 16;
                    uint32_t addr = sbase +
                        (aOff + (uint32_t)((R + aRow) * PITCH + kb + aCol)) * 2;
                    ldm_x4(af[mt], addr);
                }
#pragma unroll
                for (int pr = 0; pr < 2; pr++) {
                    int R = wn * 32 + pr * 16;
                    uint32_t addr = sbase +
                        (bOff + (uint32_t)((R + bRow) * PITCH + kb + bCol)) * 2;
                    ldm_x4(bf[pr], addr);
                }
#pragma unroll
                for (int mt = 0; mt < 2; mt++)
#pragma unroll
                    for (int nt = 0; nt < 4; nt++)
                        mma16816(acc[mt][nt], af[mt],
                                 bf[nt >> 1][(nt & 1) * 2], bf[nt >> 1][(nt & 1) * 2 + 1]);
            }
        }
        __syncthreads();
    }

    // epilogue
#pragma unroll
    for (int mt = 0; mt < 2; mt++) {
        int r0 = bm + wm * 32 + mt * 16 + (lane >> 2);
#pragma unroll
        for (int nt = 0; nt < 4; nt++) {
            int col = bn + wn * 32 + nt * 8 + (lane & 3) * 2;
            float b0 = 0.f, b1 = 0.f;
            if (BIAS) { b0 = __ldg(&bias[col]); b1 = __ldg(&bias[col + 1]); }
#pragma unroll
            for (int hh = 0; hh < 2; hh++) {
                int r = r0 + hh * 8;
                if (r < M) {
                    float v0 = acc[mt][nt][hh * 2 + 0] + b0;
                    float v1 = acc[mt][nt][hh * 2 + 1] + b1;
                    if (RELU) { v0 = fmaxf(v0, 0.f); v1 = fmaxf(v1, 0.f); }
                    if (SPLITOUT) {
                        __nv_bfloat16 h0 = __float2bfloat16(v0);
                        __nv_bfloat16 h1 = __float2bfloat16(v1);
                        __nv_bfloat162 hv = {h0, h1};
                        __nv_bfloat162 lv = {
                            __float2bfloat16(v0 - __bfloat162float(h0)),
                            __float2bfloat16(v1 - __bfloat162float(h1))};
                        *(__nv_bfloat162*)(Chi + (size_t)r * N + col) = hv;
                        *(__nv_bfloat162*)(Clo + (size_t)r * N + col) = lv;
                    } else {
                        *(float2*)(Cf + (size_t)r * N + col) = make_float2(v0, v1);
                    }
                }
            }
        }
    }
}

// ------------------------------ CSR building -------------------------------

__global__ void deg_count_k(const int* __restrict__ dst, int* d, int E) {
    int e = blockIdx.x * blockDim.x + threadIdx.x;
    if (e < E) atomicAdd(&d[dst[e]], 1);
}

// exclusive scan over degrees -> offsets + cursor copy + dinv
__global__ void scan_k(const int* __restrict__ deg, int* __restrict__ off,
                       int* __restrict__ cur, float* __restrict__ dinv, int n) {
    __shared__ int part[1024];
    int t = threadIdx.x;
    int per = (n + 1023) >> 10;
    int lo = t * per;
    int hi = min(lo + per, n);
    int s = 0;
    for (int i = lo; i < hi; i++) s += deg[i];
    part[t] = s;
    __syncthreads();
    for (int d = 1; d < 1024; d <<= 1) {
        int v = (t >= d) ? part[t - d] : 0;
        __syncthreads();
        part[t] += v;
        __syncthreads();
    }
    int run = (t == 0) ? 0 : part[t - 1];
    for (int i = lo; i < hi; i++) {
        off[i] = run;
        cur[i] = run;
        dinv[i] = rsqrtf((float)(deg[i] + 1));
        run += deg[i];
    }
    if (t == 1023) off[n] = part[1023];
}

__global__ void fill_k(const int* __restrict__ src, const int* __restrict__ dst,
                       int* cur, int* __restrict__ srcs, int E) {
    int e = blockIdx.x * blockDim.x + threadIdx.x;
    if (e < E) {
        int p = atomicAdd(&cur[dst[e]], 1);
        srcs[p] = src[e];
    }
}

// ------------------------------ aggregation --------------------------------
// Warp per node; lane owns V = C/32 contiguous columns (vectorized).

template <int C, bool BIAS, bool RELU>
__global__ void __launch_bounds__(256)
agg_k(const float* __restrict__ h, const int* __restrict__ off,
      const int* __restrict__ srcs, const float* __restrict__ dinv,
      const float* __restrict__ bias,
      __nv_bfloat16* __restrict__ Hi, __nv_bfloat16* __restrict__ Lo, int n) {
    constexpr int V = C / 32;
    int node = blockIdx.x * 8 + (threadIdx.x >> 5);
    if (node >= n) return;
    int lane = threadIdx.x & 31;
    int c = lane * V;
    float dv = dinv[node];

    float acc[V];
    {
        if (V == 4) {
            float4 v = *(const float4*)(h + (size_t)node * C + c);
            acc[0] = dv * v.x; acc[1] = dv * v.y;
            acc[2] = dv * v.z; acc[3] = dv * v.w;
        } else {
            float2 v = *(const float2*)(h + (size_t)node * C + c);
            acc[0] = dv * v.x; acc[1] = dv * v.y;
        }
    }

    const int b = off[node], e = off[node + 1];
    int i0 = b;
    for (; i0 + 32 <= e; i0 += 32) {
        int s = __ldg(&srcs[i0 + lane]);
        float nd = __ldg(&dinv[s]);
#pragma unroll 8
        for (int j = 0; j < 32; j++) {
            int ss = __shfl_sync(0xffffffffu, s, j);
            float nn = __shfl_sync(0xffffffffu, nd, j);
            const float* p = h + (size_t)ss * C + c;
            if (V == 4) {
                float4 v = *(const float4*)p;
                acc[0] = fmaf(nn, v.x, acc[0]);
                acc[1] = fmaf(nn, v.y, acc[1]);
                acc[2] = fmaf(nn, v.z, acc[2]);
                acc[3] = fmaf(nn, v.w, acc[3]);
            } else {
                float2 v = *(const float2*)p;
                acc[0] = fmaf(nn, v.x, acc[0]);
                acc[1] = fmaf(nn, v.y, acc[1]);
            }
        }
    }
    if (i0 < e) {
        int idx = i0 + lane;
        int s = 0;
        float nd = 0.f;
        if (idx < e) {
            s = __ldg(&srcs[idx]);
            nd = __ldg(&dinv[s]);
        }
        int cnt = e - i0;
#pragma unroll 4
        for (int j = 0; j < cnt; j++) {
            int ss = __shfl_sync(0xffffffffu, s, j);
            float nn = __shfl_sync(0xffffffffu, nd, j);
            const float* p = h + (size_t)ss * C + c;
            if (V == 4) {
                float4 v = *(const float4*)p;
                acc[0] = fmaf(nn, v.x, acc[0]);
                acc[1] = fmaf(nn, v.y, acc[1]);
                acc[2] = fmaf(nn, v.z, acc[2]);
                acc[3] = fmaf(nn, v.w, acc[3]);
            } else {
                float2 v = *(const float2*)p;
                acc[0] = fmaf(nn, v.x, acc[0]);
                acc[1] = fmaf(nn, v.y, acc[1]);
            }
        }
    }

#pragma unroll
    for (int k = 0; k < V; k++) {
        acc[k] *= dv;
        if (BIAS) acc[k] += __ldg(&bias[c + k]);
        if (RELU) acc[k] = fmaxf(acc[k], 0.f);
    }
#pragma unroll
    for (int k = 0; k < V; k += 2) {
        __nv_bfloat16 h0 = __float2bfloat16(acc[k]);
        __nv_bfloat16 h1 = __float2bfloat16(acc[k + 1]);
        __nv_bfloat162 hv = {h0, h1};
        __nv_bfloat162 lv = {__float2bfloat16(acc[k] - __bfloat162float(h0)),
                             __float2bfloat16(acc[k + 1] - __bfloat162float(h1))};
        *(__nv_bfloat162*)(Hi + (size_t)node * C + c + k) = hv;
        *(__nv_bfloat162*)(Lo + (size_t)node * C + c + k) = lv;
    }
}

// ------------------------------ split / misc -------------------------------

__global__ void asplit_k(const float* __restrict__ A, __nv_bfloat16* __restrict__ hi,
                         __nv_bfloat16* __restrict__ lo, long total4) {
    long t = (long)blockIdx.x * blockDim.x + threadIdx.x;
    if (t >= total4) return;
    float4 v = *(const float4*)(A + t * 4);
    __nv_bfloat16 h0 = __float2bfloat16(v.x), h1 = __float2bfloat16(v.y);
    __nv_bfloat16 h2 = __float2bfloat16(v.z), h3 = __float2bfloat16(v.w);
    __nv_bfloat162 H0 = {h0, h1}, H1 = {h2, h3};
    __nv_bfloat162 L0 = {__float2bfloat16(v.x - __bfloat162float(h0)),
                         __float2bfloat16(v.y - __bfloat162float(h1))};
    __nv_bfloat162 L1 = {__float2bfloat16(v.z - __bfloat162float(h2)),
                         __float2bfloat16(v.w - __bfloat162float(h3))};
    *(__nv_bfloat162*)(hi + t * 4) = H0;
    *(__nv_bfloat162*)(hi + t * 4 + 2) = H1;
    *(__nv_bfloat162*)(lo + t * 4) = L0;
    *(__nv_bfloat162*)(lo + t * 4 + 2) = L1;
}

// all 6 weight transposes+splits in one launch
struct WJobs {
    const float* W[6];
    int K[6], N[6], off[6], elems[6];
};

__global__ void wsplit_all_k(WJobs P, __nv_bfloat16* __restrict__ hi,
                             __nv_bfloat16* __restrict__ lo) {
    int i = blockIdx.x * blockDim.x + threadIdx.x;
#pragma unroll
    for (int j = 0; j < 6; j++) {
        if (i < P.elems[j]) {
            int K = P.K[j], N = P.N[j];
            int n = i / K, k = i % K;
            float v = P.W[j][(long)k * N + n];
            __nv_bfloat16 h = __float2bfloat16(v);
            hi[P.off[j] + i] = h;
            lo[P.off[j] + i] = __float2bfloat16(v - __bfloat162float(h));
            return;
        }
        i -= P.elems[j];
    }
}

// cb[j] = sum_k b1[k]*W[k,j] + b2[j], ILP-4 partial sums (short dep chains)
__global__ void combine_bias_k(const float* __restrict__ b1, const float* __restrict__ W,
                               const float* __restrict__ b2, float* __restrict__ cb,
                               int K, int N) {
    int j = blockIdx.x * blockDim.x + threadIdx.x;
    if (j >= N) return;
    float s0 = 0.f, s1 = 0.f, s2 = 0.f, s3 = 0.f;
    for (int k = 0; k < K; k += 4) {
        s0 = fmaf(b1[k + 0], W[(long)(k + 0) * N + j], s0);
        s1 = fmaf(b1[k + 1], W[(long)(k + 1) * N + j], s1);
        s2 = fmaf(b1[k + 2], W[(long)(k + 2) * N + j], s2);
        s3 = fmaf(b1[k + 3], W[(long)(k + 3) * N + j], s3);
    }
    cb[j] = (s0 + s1) + (s2 + s3) + b2[j];
}

// --------------------------------- launch ----------------------------------

static inline int cdiv(long a, long b) { return (int)((a + b - 1) / b); }

constexpr int MM_SMEM = (2 * 2 * 128 * 40 + 2 * 2 * 64 * 40) * 2;  // 61440B

template <int K, bool BIAS, bool RELU, bool SPLITOUT>
static void run_mm(const __nv_bfloat16* Ahi, const __nv_bfloat16* Alo,
                   const __nv_bfloat16* Bhi, const __nv_bfloat16* Blo,
                   const float* bias, float* Cf, __nv_bfloat16* Chi,
                   __nv_bfloat16* Clo, int M, int N) {
    cudaFuncSetAttribute(mm_k<K, BIAS, RELU, SPLITOUT>,
                         cudaFuncAttributeMaxDynamicSharedMemorySize, MM_SMEM);
    dim3 g(N / 64, cdiv(M, 128));
    mm_k<K, BIAS, RELU, SPLITOUT><<<g, 256, MM_SMEM>>>(
        Ahi, Alo, Bhi, Blo, bias, Cf, Chi, Clo, M, N);
}

extern "C" void kernel_launch(void* const* d_in, const int* in_sizes, int n_in,
                              void* d_out, int out_size) {
    const float* x   = (const float*)d_in[0];
    const int*   ei  = (const int*)d_in[1];
    const float* eW1 = (const float*)d_in[2];
    const float* eb1 = (const float*)d_in[3];
    const float* eW2 = (const float*)d_in[4];
    const float* eb2 = (const float*)d_in[5];
    const float* eWf = (const float*)d_in[6];
    const float* ebf = (const float*)d_in[7];
    const float* dW1 = (const float*)d_in[8];
    const float* db1 = (const float*)d_in[9];
    const float* dW2 = (const float*)d_in[10];
    const float* db2 = (const float*)d_in[11];
    const float* dWf = (const float*)d_in[12];
    const float* dbf = (const float*)d_in[13];
    float* out = (float*)d_out;

    const int M = in_sizes[0] / 128;  // 50000
    const int E = in_sizes[1] / 2;    // 800000
    const int* src = ei;
    const int* dst = ei + E;

    float *dinv, *bufA, *cbias;
    int *degi, *off, *cur, *srcs;
    __nv_bfloat16 *Ahi, *Alo, *Bh, *Bl, *Whi, *Wlo;
    cudaGetSymbolAddress((void**)&dinv, g_dinv);
    cudaGetSymbolAddress((void**)&degi, g_degi);
    cudaGetSymbolAddress((void**)&off, g_off);
    cudaGetSymbolAddress((void**)&cur, g_cur);
    cudaGetSymbolAddress((void**)&srcs, g_srcs);
    cudaGetSymbolAddress((void**)&bufA, g_bufA);
    cudaGetSymbolAddress((void**)&cbias, g_cbias);
    cudaGetSymbolAddress((void**)&Ahi, g_Ahi);
    cudaGetSymbolAddress((void**)&Alo, g_Alo);
    cudaGetSymbolAddress((void**)&Bh, g_Bhi);
    cudaGetSymbolAddress((void**)&Bl, g_Blo);
    cudaGetSymbolAddress((void**)&Whi, g_Whi);
    cudaGetSymbolAddress((void**)&Wlo, g_Wlo);

    const int O_EW1 = 0;      // 128x128
    const int O_EW2 = 16384;  // 64x128
    const int O_EWF = 24576;  // 64x64
    const int O_DW1 = 28672;  // 256x64
    const int O_DW2 = 45056;  // 128x256
    const int O_DWF = 77824;  // 1024x128

    const int T = 256;

    static cudaStream_t s2 = nullptr;
    static cudaEvent_t evFork = nullptr, evJoin = nullptr;
    if (!s2) {
        cudaStreamCreateWithFlags(&s2, cudaStreamNonBlocking);
        cudaEventCreateWithFlags(&evFork, cudaEventDisableTiming);
        cudaEventCreateWithFlags(&evJoin, cudaEventDisableTiming);
    }

    // ---- fork: CSR build on s2 ----
    cudaEventRecord(evFork, 0);
    cudaStreamWaitEvent(s2, evFork, 0);
    cudaMemsetAsync(degi, 0, M * sizeof(int), s2);
    deg_count_k<<<cdiv(E, T), T, 0, s2>>>(dst, degi, E);
    scan_k<<<1, 1024, 0, s2>>>(degi, off, cur, dinv, M);
    fill_k<<<cdiv(E, T), T, 0, s2>>>(src, dst, cur, srcs, E);
    cudaEventRecord(evJoin, s2);

    // ---- main stream: weight prep + combined biases + first GEMM ----
    {
        WJobs P;
        const float* Ws[6] = {eW1, eW2, eWf, dW1, dW2, dWf};
        int Ks[6] = {128, 128, 64, 64, 256, 128};
        int Ns[6] = {128, 64, 64, 256, 128, 1024};
        int Os[6] = {O_EW1, O_EW2, O_EWF, O_DW1, O_DW2, O_DWF};
        int total = 0;
        for (int j = 0; j < 6; j++) {
            P.W[j] = Ws[j]; P.K[j] = Ks[j]; P.N[j] = Ns[j];
            P.off[j] = Os[j]; P.elems[j] = Ks[j] * Ns[j];
            total += P.elems[j];
        }
        wsplit_all_k<<<cdiv(total, T), T>>>(P, Whi, Wlo);
    }
    combine_bias_k<<<1, 64>>>(eb2, eWf, ebf, cbias, 64, 64);
    combine_bias_k<<<cdiv(1024, 128), 128>>>(db2, dWf, dbf, cbias + 1024, 128, 1024);

    // enc GCN1 linear part: t1 = x@eW1 (independent of CSR)
    asplit_k<<<cdiv((long)M * 32, T), T>>>(x, Ahi, Alo, (long)M * 32);
    run_mm<128, false, false, false>(Ahi, Alo, Whi + O_EW1, Wlo + O_EW1,
                                     nullptr, bufA, nullptr, nullptr, M, 128);

    // ---- join: aggregation needs CSR ----
    cudaStreamWaitEvent(0, evJoin, 0);

    // h1 = relu(A(t1)+eb1) -> split Bh/Bl [M,128]
    agg_k<128, true, true><<<cdiv(M, 8), 256>>>(bufA, off, srcs, dinv, eb1, Bh, Bl, M);

    // enc GCN2: t2 = h1@eW2 ; A(t2) -> split Ahi/Alo [M,64]
    run_mm<128, false, false, false>(Bh, Bl, Whi + O_EW2, Wlo + O_EW2,
                                     nullptr, bufA, nullptr, nullptr, M, 64);
    agg_k<64, false, false><<<cdiv(M, 8), 256>>>(bufA, off, srcs, dinv, nullptr, Ahi, Alo, M);

    // z = a2@eWf + cb -> fp32 bufA [M,64]
    run_mm<64, true, false, false>(Ahi, Alo, Whi + O_EWF, Wlo + O_EWF,
                                   cbias, bufA, nullptr, nullptr, M, 64);

    // dec GCN1: A(z) -> split Bh/Bl ; h = relu(A(z)@dW1+db1) -> split Ahi/Alo [M,256]
    agg_k<64, false, false><<<cdiv(M, 8), 256>>>(bufA, off, srcs, dinv, nullptr, Bh, Bl, M);
    run_mm<64, true, true, true>(Bh, Bl, Whi + O_DW1, Wlo + O_DW1,
                                 db1, nullptr, Ahi, Alo, M, 256);

    // dec GCN2: t = h@dW2 -> fp32 ; A(t) -> split Bh/Bl [M,128]
    run_mm<256, false, false, false>(Ahi, Alo, Whi + O_DW2, Wlo + O_DW2,
                                     nullptr, bufA, nullptr, nullptr, M, 128);
    agg_k<128, false, false><<<cdiv(M, 8), 256>>>(bufA, off, srcs, dinv, nullptr, Bh, Bl, M);

    // out = a4@dWf + cb2
    run_mm<128, true, false, false>(Bh, Bl, Whi + O_DWF, Wlo + O_DWF,
                                    cbias + 1024, out, nullptr, nullptr, M, 1024);
}

// round 13
// speedup vs baseline: 1.0427x; 1.0084x over previous
#include <cuda_runtime.h>
#include <cuda_bf16.h>
#include <cstdint>

// ===========================================================================
// GCN auto-encoder.
//  - GEMMs: mma.sync m16n8k16 bf16 (HMMA), bf16x3 split (hi*hi+hi*lo+lo*hi,
//    fp32 accum) ~ fp32 accuracy. cp.async 2-stage pipeline + ldmatrix frags.
//    BM=128, BN=64, 256 threads. AF32 variant converts fp32 A in-register
//    (fuses the input split into the first GEMM).
//  - Aggregation: per-launch CSR, warp-per-node gather-reduce (unroll-8),
//    fused bias/relu/bf16-split epilogue. No float atomics.
//  - CSR build on forked stream (R8 topology); combine_bias ILP-4.
// ===========================================================================

constexpr int MAXN = 50000;
constexpr int MAXE = 800000;

__device__ __align__(256) float g_dinv[MAXN];
__device__ __align__(256) int   g_degi[MAXN];
__device__ __align__(256) int   g_off[MAXN + 1];
__device__ __align__(256) int   g_cur[MAXN];
__device__ __align__(256) int   g_srcs[MAXE];
__device__ __align__(256) float g_bufA[(size_t)MAXN * 128];
__device__ __align__(256) float g_cbias[2048];
__device__ __align__(256) __nv_bfloat16 g_Ahi[(size_t)MAXN * 256];
__device__ __align__(256) __nv_bfloat16 g_Alo[(size_t)MAXN * 256];
__device__ __align__(256) __nv_bfloat16 g_Bhi[(size_t)MAXN * 256];
__device__ __align__(256) __nv_bfloat16 g_Blo[(size_t)MAXN * 256];
__device__ __align__(256) __nv_bfloat16 g_Whi[262144];
__device__ __align__(256) __nv_bfloat16 g_Wlo[262144];

// ------------------------------- helpers -----------------------------------

__device__ __forceinline__ uint32_t smem_u32(const void* p) {
    uint32_t a;
    asm("{ .reg .u64 t; cvta.to.shared.u64 t, %1; cvt.u32.u64 %0, t; }"
        : "=r"(a) : "l"(p));
    return a;
}

__device__ __forceinline__ void cp16(uint32_t dst, const void* src, bool pred) {
    asm volatile("cp.async.cg.shared.global [%0], [%1], 16, %2;"
                 :: "r"(dst), "l"(src), "r"(pred ? 16 : 0));
}
__device__ __forceinline__ void cp_commit() {
    asm volatile("cp.async.commit_group;");
}
__device__ __forceinline__ void cp_wait1() {
    asm volatile("cp.async.wait_group 1;");
}

__device__ __forceinline__ void ldm_x4(uint32_t r[4], uint32_t addr) {
    asm volatile("ldmatrix.sync.aligned.m8n8.x4.shared.b16 {%0,%1,%2,%3}, [%4];"
                 : "=r"(r[0]), "=r"(r[1]), "=r"(r[2]), "=r"(r[3]) : "r"(addr));
}

__device__ __forceinline__ void mma16816(float c[4], const uint32_t a[4],
                                         const uint32_t b0, const uint32_t b1) {
    asm volatile(
        "mma.sync.aligned.m16n8k16.row.col.f32.bf16.bf16.f32 "
        "{%0,%1,%2,%3}, {%4,%5,%6,%7}, {%8,%9}, {%0,%1,%2,%3};"
        : "+f"(c[0]), "+f"(c[1]), "+f"(c[2]), "+f"(c[3])
        : "r"(a[0]), "r"(a[1]), "r"(a[2]), "r"(a[3]), "r"(b0), "r"(b1));
}

__device__ __forceinline__ uint32_t pack_bf162(__nv_bfloat16 a, __nv_bfloat16 b) {
    __nv_bfloat162 v = {a, b};
    return *(uint32_t*)&v;
}

// ------------------------------- tensor GEMM -------------------------------
// C[M,N] = A[M,K] @ W,  W pre-transposed+split to [N,K] bf16 hi/lo.
// BM=128, BN=64, BK=32, 256 threads (8 warps, 4Mx2N), 2-stage cp.async.
// AF32: A given as fp32; hi/lo fragments built in-register (split fused).

template <int K, bool AF32, bool BIAS, bool RELU, bool SPLITOUT>
__global__ void __launch_bounds__(256)
mm_k(const void* __restrict__ Apv, const __nv_bfloat16* __restrict__ Alo,
     const __nv_bfloat16* __restrict__ Bhi, const __nv_bfloat16* __restrict__ Blo,
     const float* __restrict__ bias, float* __restrict__ Cf,
     __nv_bfloat16* __restrict__ Chi, __nv_bfloat16* __restrict__ Clo,
     int M, int N) {
    constexpr int BM = 128, BK = 32, PITCH = 40;   // bf16 path: 80B rows
    constexpr int PITCHF = 40;                     // fp32 path: 160B rows
    constexpr int KT = K / BK;
    // smem layout:
    //  AF32:  A fp32 [2 stages][128][PITCHF] floats (40960B), then B at 40960
    //  else:  A bf16 [2 stages][2 mats][128][PITCH]           , then B at 40960
    constexpr uint32_t BOFF_BYTES = 2 * 2 * 128 * PITCH * 2;   // 40960
    extern __shared__ char smem[];
    const uint32_t sbase = smem_u32(smem);
    const __nv_bfloat16* Ahi = (const __nv_bfloat16*)Apv;
    const float* Af = (const float*)Apv;
    float* smemF = (float*)smem;

    const int tid = threadIdx.x;
    const int lane = tid & 31, wid = tid >> 5;
    const int wm = wid & 3, wn = wid >> 2;
    const int bm = blockIdx.y * BM, bn = blockIdx.x * 64;

    float acc[2][4][4];
#pragma unroll
    for (int i = 0; i < 2; i++)
#pragma unroll
        for (int j = 0; j < 4; j++)
#pragma unroll
            for (int l = 0; l < 4; l++) acc[i][j][l] = 0.f;

    auto load_stage = [&](int st, int k0) {
        if (AF32) {
#pragma unroll
            for (int l = 0; l < 4; l++) {  // A fp32: 1024 16B chunks
                int idx = tid + l * 256;
                int row = idx >> 3, q = idx & 7;  // q*4 floats
                int g = bm + row;
                const float* src = Af + (size_t)g * K + k0 + q * 4;
                uint32_t dst = sbase +
                    (uint32_t)(((st * 128 + row) * PITCHF + q * 4) * 4);
                cp16(dst, src, g < M);
            }
        } else {
#pragma unroll
            for (int l = 0; l < 4; l++) {  // A bf16: 1024 16B chunks (2 mats)
                int idx = tid + l * 256;
                int mat = idx >> 9, rem = idx & 511, row = rem >> 2, q = rem & 3;
                int g = bm + row;
                const __nv_bfloat16* src =
                    (mat ? Alo : Ahi) + (size_t)g * K + k0 + q * 8;
                uint32_t dst = sbase +
                    (uint32_t)((((st * 2 + mat) * 128 + row) * PITCH + q * 8) * 2);
                cp16(dst, src, g < M);
            }
        }
#pragma unroll
        for (int l = 0; l < 2; l++) {  // B: 512 16B chunks
            int idx = tid + l * 256;
            int mat = idx >> 8, rem = idx & 255, row = rem >> 2, q = rem & 3;
            const __nv_bfloat16* src =
                (mat ? Blo : Bhi) + (size_t)(bn + row) * K + k0 + q * 8;
            uint32_t dst = sbase + BOFF_BYTES +
                (uint32_t)((((st * 2 + mat) * 64 + row) * PITCH + q * 8) * 2);
            cp16(dst, src, true);
        }
    };

    // per-lane frag address components
    const int aRow = lane & 15, aCol = (lane >> 4) * 8;        // ldmatrix A
    const int afRow = lane >> 2, afK = (lane & 3) * 2;         // fp32 A frags
    const int bRow = ((lane >> 4) & 1) * 8 + (lane & 7);       // ldmatrix B
    const int bCol = ((lane >> 3) & 1) * 8;

    load_stage(0, 0);
    cp_commit();

    for (int kt = 0; kt < KT; kt++) {
        if (kt + 1 < KT) load_stage((kt + 1) & 1, (kt + 1) * BK);
        cp_commit();
        cp_wait1();
        __syncthreads();

        const int st = kt & 1;
        const uint32_t bOff0 = BOFF_BYTES + (uint32_t)((st * 2) * 64 * PITCH) * 2;
        const uint32_t bOff1 = BOFF_BYTES + (uint32_t)((st * 2 + 1) * 64 * PITCH) * 2;

#pragma unroll
        for (int ks = 0; ks < 2; ks++) {
            const int kb = ks * 16;
            uint32_t afh[2][4], afl[2][4];

            if (AF32) {
                const int aBaseF = st * 128 * PITCHF;
#pragma unroll
                for (int mt = 0; mt < 2; mt++) {
                    int R = wm * 32 + mt * 16;
#pragma unroll
                    for (int i = 0; i < 4; i++) {
                        int rr = R + afRow + (i & 1) * 8;
                        int kk = kb + afK + (i >> 1) * 8;
                        float2 v = *(const float2*)(smemF + aBaseF + rr * PITCHF + kk);
                        __nv_bfloat16 h0 = __float2bfloat16(v.x);
                        __nv_bfloat16 h1 = __float2bfloat16(v.y);
                        afh[mt][i] = pack_bf162(h0, h1);
                        afl[mt][i] = pack_bf162(
                            __float2bfloat16(v.x - __bfloat162float(h0)),
                            __float2bfloat16(v.y - __bfloat162float(h1)));
                    }
                }
            } else {
                const uint32_t aOff0 = (uint32_t)((st * 2) * 128 * PITCH) * 2;
                const uint32_t aOff1 = (uint32_t)((st * 2 + 1) * 128 * PITCH) * 2;
#pragma unroll
                for (int mt = 0; mt < 2; mt++) {
                    int R = wm * 32 + mt * 16;
                    uint32_t rel = (uint32_t)((R + aRow) * PITCH + kb + aCol) * 2;
                    ldm_x4(afh[mt], sbase + aOff0 + rel);
                    ldm_x4(afl[mt], sbase + aOff1 + rel);
                }
            }

            // passes: p0 = ah*bh, p1 = ah*bl, p2 = al*bh
#pragma unroll
            for (int p = 0; p < 3; p++) {
                const uint32_t bOff = (p == 1) ? bOff1 : bOff0;
                uint32_t (*af)[4] = (p == 2) ? afl : afh;
                uint32_t bf[2][4];
#pragma unroll
                for (int pr = 0; pr < 2; pr++) {
                    int R = wn * 32 + pr * 16;
                    uint32_t addr = sbase + bOff +
                        (uint32_t)((R + bRow) * PITCH + kb + bCol) * 2;
                    ldm_x4(bf[pr], addr);
                }
#pragma unroll
                for (int mt = 0; mt < 2; mt++)
#pragma unroll
                    for (int nt = 0; nt < 4; nt++)
                        mma16816(acc[mt][nt], af[mt],
                                 bf[nt >> 1][(nt & 1) * 2], bf[nt >> 1][(nt & 1) * 2 + 1]);
            }
        }
        __syncthreads();
    }

    // epilogue
#pragma unroll
    for (int mt = 0; mt < 2; mt++) {
        int r0 = bm + wm * 32 + mt * 16 + (lane >> 2);
#pragma unroll
        for (int nt = 0; nt < 4; nt++) {
            int col = bn + wn * 32 + nt * 8 + (lane & 3) * 2;
            float b0 = 0.f, b1 = 0.f;
            if (BIAS) { b0 = __ldg(&bias[col]); b1 = __ldg(&bias[col + 1]); }
#pragma unroll
            for (int hh = 0; hh < 2; hh++) {
                int r = r0 + hh * 8;
                if (r < M) {
                    float v0 = acc[mt][nt][hh * 2 + 0] + b0;
                    float v1 = acc[mt][nt][hh * 2 + 1] + b1;
                    if (RELU) { v0 = fmaxf(v0, 0.f); v1 = fmaxf(v1, 0.f); }
                    if (SPLITOUT) {
                        __nv_bfloat16 h0 = __float2bfloat16(v0);
                        __nv_bfloat16 h1 = __float2bfloat16(v1);
                        __nv_bfloat162 hv = {h0, h1};
                        __nv_bfloat162 lv = {
                            __float2bfloat16(v0 - __bfloat162float(h0)),
                            __float2bfloat16(v1 - __bfloat162float(h1))};
                        *(__nv_bfloat162*)(Chi + (size_t)r * N + col) = hv;
                        *(__nv_bfloat162*)(Clo + (size_t)r * N + col) = lv;
                    } else {
                        *(float2*)(Cf + (size_t)r * N + col) = make_float2(v0, v1);
                    }
                }
            }
        }
    }
}

// ------------------------------ CSR building -------------------------------

__global__ void deg_count_k(const int* __restrict__ dst, int* d, int E) {
    int e = blockIdx.x * blockDim.x + threadIdx.x;
    if (e < E) atomicAdd(&d[dst[e]], 1);
}

__global__ void scan_k(const int* __restrict__ deg, int* __restrict__ off,
                       int* __restrict__ cur, float* __restrict__ dinv, int n) {
    __shared__ int part[1024];
    int t = threadIdx.x;
    int per = (n + 1023) >> 10;
    int lo = t * per;
    int hi = min(lo + per, n);
    int s = 0;
    for (int i = lo; i < hi; i++) s += deg[i];
    part[t] = s;
    __syncthreads();
    for (int d = 1; d < 1024; d <<= 1) {
        int v = (t >= d) ? part[t - d] : 0;
        __syncthreads();
        part[t] += v;
        __syncthreads();
    }
    int run = (t == 0) ? 0 : part[t - 1];
    for (int i = lo; i < hi; i++) {
        off[i] = run;
        cur[i] = run;
        dinv[i] = rsqrtf((float)(deg[i] + 1));
        run += deg[i];
    }
    if (t == 1023) off[n] = part[1023];
}

__global__ void fill_k(const int* __restrict__ src, const int* __restrict__ dst,
                       int* cur, int* __restrict__ srcs, int E) {
    int e = blockIdx.x * blockDim.x + threadIdx.x;
    if (e < E) {
        int p = atomicAdd(&cur[dst[e]], 1);
        srcs[p] = src[e];
    }
}

// ------------------------------ aggregation --------------------------------

template <int C, bool BIAS, bool RELU>
__global__ void __launch_bounds__(256)
agg_k(const float* __restrict__ h, const int* __restrict__ off,
      const int* __restrict__ srcs, const float* __restrict__ dinv,
      const float* __restrict__ bias,
      __nv_bfloat16* __restrict__ Hi, __nv_bfloat16* __restrict__ Lo, int n) {
    constexpr int V = C / 32;
    int node = blockIdx.x * 8 + (threadIdx.x >> 5);
    if (node >= n) return;
    int lane = threadIdx.x & 31;
    int c = lane * V;
    float dv = dinv[node];

    float acc[V];
    {
        if (V == 4) {
            float4 v = *(const float4*)(h + (size_t)node * C + c);
            acc[0] = dv * v.x; acc[1] = dv * v.y;
            acc[2] = dv * v.z; acc[3] = dv * v.w;
        } else {
            float2 v = *(const float2*)(h + (size_t)node * C + c);
            acc[0] = dv * v.x; acc[1] = dv * v.y;
        }
    }

    const int b = off[node], e = off[node + 1];
    int i0 = b;
    for (; i0 + 32 <= e; i0 += 32) {
        int s = __ldg(&srcs[i0 + lane]);
        float nd = __ldg(&dinv[s]);
#pragma unroll 8
        for (int j = 0; j < 32; j++) {
            int ss = __shfl_sync(0xffffffffu, s, j);
            float nn = __shfl_sync(0xffffffffu, nd, j);
            const float* p = h + (size_t)ss * C + c;
            if (V == 4) {
                float4 v = *(const float4*)p;
                acc[0] = fmaf(nn, v.x, acc[0]);
                acc[1] = fmaf(nn, v.y, acc[1]);
                acc[2] = fmaf(nn, v.z, acc[2]);
                acc[3] = fmaf(nn, v.w, acc[3]);
            } else {
                float2 v = *(const float2*)p;
                acc[0] = fmaf(nn, v.x, acc[0]);
                acc[1] = fmaf(nn, v.y, acc[1]);
            }
        }
    }
    if (i0 < e) {
        int idx = i0 + lane;
        int s = 0;
        float nd = 0.f;
        if (idx < e) {
            s = __ldg(&srcs[idx]);
            nd = __ldg(&dinv[s]);
        }
        int cnt = e - i0;
#pragma unroll 4
        for (int j = 0; j < cnt; j++) {
            int ss = __shfl_sync(0xffffffffu, s, j);
            float nn = __shfl_sync(0xffffffffu, nd, j);
            const float* p = h + (size_t)ss * C + c;
            if (V == 4) {
                float4 v = *(const float4*)p;
                acc[0] = fmaf(nn, v.x, acc[0]);
                acc[1] = fmaf(nn, v.y, acc[1]);
                acc[2] = fmaf(nn, v.z, acc[2]);
                acc[3] = fmaf(nn, v.w, acc[3]);
            } else {
                float2 v = *(const float2*)p;
                acc[0] = fmaf(nn, v.x, acc[0]);
                acc[1] = fmaf(nn, v.y, acc[1]);
            }
        }
    }

#pragma unroll
    for (int k = 0; k < V; k++) {
        acc[k] *= dv;
        if (BIAS) acc[k] += __ldg(&bias[c + k]);
        if (RELU) acc[k] = fmaxf(acc[k], 0.f);
    }
#pragma unroll
    for (int k = 0; k < V; k += 2) {
        __nv_bfloat16 h0 = __float2bfloat16(acc[k]);
        __nv_bfloat16 h1 = __float2bfloat16(acc[k + 1]);
        __nv_bfloat162 hv = {h0, h1};
        __nv_bfloat162 lv = {__float2bfloat16(acc[k] - __bfloat162float(h0)),
                             __float2bfloat16(acc[k + 1] - __bfloat162float(h1))};
        *(__nv_bfloat162*)(Hi + (size_t)node * C + c + k) = hv;
        *(__nv_bfloat162*)(Lo + (size_t)node * C + c + k) = lv;
    }
}

// ------------------------------ split / misc -------------------------------

// all 6 weight transposes+splits in one launch
struct WJobs {
    const float* W[6];
    int K[6], N[6], off[6], elems[6];
};

__global__ void wsplit_all_k(WJobs P, __nv_bfloat16* __restrict__ hi,
                             __nv_bfloat16* __restrict__ lo) {
    int i = blockIdx.x * blockDim.x + threadIdx.x;
#pragma unroll
    for (int j = 0; j < 6; j++) {
        if (i < P.elems[j]) {
            int K = P.K[j], N = P.N[j];
            int n = i / K, k = i % K;
            float v = P.W[j][(long)k * N + n];
            __nv_bfloat16 h = __float2bfloat16(v);
            hi[P.off[j] + i] = h;
            lo[P.off[j] + i] = __float2bfloat16(v - __bfloat162float(h));
            return;
        }
        i -= P.elems[j];
    }
}

// cb[j] = sum_k b1[k]*W[k,j] + b2[j], ILP-4 partial sums
__global__ void combine_bias_k(const float* __restrict__ b1, const float* __restrict__ W,
                               const float* __restrict__ b2, float* __restrict__ cb,
                               int K, int N) {
    int j = blockIdx.x * blockDim.x + threadIdx.x;
    if (j >= N) return;
    float s0 = 0.f, s1 = 0.f, s2 = 0.f, s3 = 0.f;
    for (int k = 0; k < K; k += 4) {
        s0 = fmaf(b1[k + 0], W[(long)(k + 0) * N + j], s0);
        s1 = fmaf(b1[k + 1], W[(long)(k + 1) * N + j], s1);
        s2 = fmaf(b1[k + 2], W[(long)(k + 2) * N + j], s2);
        s3 = fmaf(b1[k + 3], W[(long)(k + 3) * N + j], s3);
    }
    cb[j] = (s0 + s1) + (s2 + s3) + b2[j];
}

// --------------------------------- launch ----------------------------------

static inline int cdiv(long a, long b) { return (int)((a + b - 1) / b); }

constexpr int MM_SMEM = (2 * 2 * 128 * 40 + 2 * 2 * 64 * 40) * 2;  // 61440B

template <int K, bool AF32, bool BIAS, bool RELU, bool SPLITOUT>
static void run_mm(const void* A, const __nv_bfloat16* Alo,
                   const __nv_bfloat16* Bhi, const __nv_bfloat16* Blo,
                   const float* bias, float* Cf, __nv_bfloat16* Chi,
                   __nv_bfloat16* Clo, int M, int N) {
    cudaFuncSetAttribute(mm_k<K, AF32, BIAS, RELU, SPLITOUT>,
                         cudaFuncAttributeMaxDynamicSharedMemorySize, MM_SMEM);
    dim3 g(N / 64, cdiv(M, 128));
    mm_k<K, AF32, BIAS, RELU, SPLITOUT><<<g, 256, MM_SMEM>>>(
        A, Alo, Bhi, Blo, bias, Cf, Chi, Clo, M, N);
}

extern "C" void kernel_launch(void* const* d_in, const int* in_sizes, int n_in,
                              void* d_out, int out_size) {
    const float* x   = (const float*)d_in[0];
    const int*   ei  = (const int*)d_in[1];
    const float* eW1 = (const float*)d_in[2];
    const float* eb1 = (const float*)d_in[3];
    const float* eW2 = (const float*)d_in[4];
    const float* eb2 = (const float*)d_in[5];
    const float* eWf = (const float*)d_in[6];
    const float* ebf = (const float*)d_in[7];
    const float* dW1 = (const float*)d_in[8];
    const float* db1 = (const float*)d_in[9];
    const float* dW2 = (const float*)d_in[10];
    const float* db2 = (const float*)d_in[11];
    const float* dWf = (const float*)d_in[12];
    const float* dbf = (const float*)d_in[13];
    float* out = (float*)d_out;

    const int M = in_sizes[0] / 128;  // 50000
    const int E = in_sizes[1] / 2;    // 800000
    const int* src = ei;
    const int* dst = ei + E;

    float *dinv, *bufA, *cbias;
    int *degi, *off, *cur, *srcs;
    __nv_bfloat16 *Ahi, *Alo, *Bh, *Bl, *Whi, *Wlo;
    cudaGetSymbolAddress((void**)&dinv, g_dinv);
    cudaGetSymbolAddress((void**)&degi, g_degi);
    cudaGetSymbolAddress((void**)&off, g_off);
    cudaGetSymbolAddress((void**)&cur, g_cur);
    cudaGetSymbolAddress((void**)&srcs, g_srcs);
    cudaGetSymbolAddress((void**)&bufA, g_bufA);
    cudaGetSymbolAddress((void**)&cbias, g_cbias);
    cudaGetSymbolAddress((void**)&Ahi, g_Ahi);
    cudaGetSymbolAddress((void**)&Alo, g_Alo);
    cudaGetSymbolAddress((void**)&Bh, g_Bhi);
    cudaGetSymbolAddress((void**)&Bl, g_Blo);
    cudaGetSymbolAddress((void**)&Whi, g_Whi);
    cudaGetSymbolAddress((void**)&Wlo, g_Wlo);

    const int O_EW1 = 0;      // 128x128
    const int O_EW2 = 16384;  // 64x128
    const int O_EWF = 24576;  // 64x64
    const int O_DW1 = 28672;  // 256x64
    const int O_DW2 = 45056;  // 128x256
    const int O_DWF = 77824;  // 1024x128

    const int T = 256;

    static cudaStream_t s2 = nullptr;
    static cudaEvent_t evFork = nullptr, evJoin = nullptr;
    if (!s2) {
        cudaStreamCreateWithFlags(&s2, cudaStreamNonBlocking);
        cudaEventCreateWithFlags(&evFork, cudaEventDisableTiming);
        cudaEventCreateWithFlags(&evJoin, cudaEventDisableTiming);
    }

    // ---- fork: CSR build on s2 ----
    cudaEventRecord(evFork, 0);
    cudaStreamWaitEvent(s2, evFork, 0);
    cudaMemsetAsync(degi, 0, M * sizeof(int), s2);
    deg_count_k<<<cdiv(E, T), T, 0, s2>>>(dst, degi, E);
    scan_k<<<1, 1024, 0, s2>>>(degi, off, cur, dinv, M);
    fill_k<<<cdiv(E, T), T, 0, s2>>>(src, dst, cur, srcs, E);
    cudaEventRecord(evJoin, s2);

    // ---- main stream: weight prep + combined biases + first GEMM ----
    {
        WJobs P;
        const float* Ws[6] = {eW1, eW2, eWf, dW1, dW2, dWf};
        int Ks[6] = {128, 128, 64, 64, 256, 128};
        int Ns[6] = {128, 64, 64, 256, 128, 1024};
        int Os[6] = {O_EW1, O_EW2, O_EWF, O_DW1, O_DW2, O_DWF};
        int total = 0;
        for (int j = 0; j < 6; j++) {
            P.W[j] = Ws[j]; P.K[j] = Ks[j]; P.N[j] = Ns[j];
            P.off[j] = Os[j]; P.elems[j] = Ks[j] * Ns[j];
            total += P.elems[j];
        }
        wsplit_all_k<<<cdiv(total, T), T>>>(P, Whi, Wlo);
    }
    combine_bias_k<<<1, 64>>>(eb2, eWf, ebf, cbias, 64, 64);
    combine_bias_k<<<cdiv(1024, 128), 128>>>(db2, dWf, dbf, cbias + 1024, 128, 1024);

    // enc GCN1 linear part: t1 = x@eW1 (fp32 A, split fused in-kernel)
    run_mm<128, true, false, false, false>(x, nullptr, Whi + O_EW1, Wlo + O_EW1,
                                           nullptr, bufA, nullptr, nullptr, M, 128);

    // ---- join: aggregation needs CSR ----
    cudaStreamWaitEvent(0, evJoin, 0);

    // h1 = relu(A(t1)+eb1) -> split Bh/Bl [M,128]
    agg_k<128, true, true><<<cdiv(M, 8), 256>>>(bufA, off, srcs, dinv, eb1, Bh, Bl, M);

    // enc GCN2: t2 = h1@eW2 ; A(t2) -> split Ahi/Alo [M,64]
    run_mm<128, false, false, false, false>(Bh, Bl, Whi + O_EW2, Wlo + O_EW2,
                                            nullptr, bufA, nullptr, nullptr, M, 64);
    agg_k<64, false, false><<<cdiv(M, 8), 256>>>(bufA, off, srcs, dinv, nullptr, Ahi, Alo, M);

    // z = a2@eWf + cb -> fp32 bufA [M,64]
    run_mm<64, false, true, false, false>(Ahi, Alo, Whi + O_EWF, Wlo + O_EWF,
                                          cbias, bufA, nullptr, nullptr, M, 64);

    // dec GCN1: A(z) -> split Bh/Bl ; h = relu(A(z)@dW1+db1) -> split Ahi/Alo [M,256]
    agg_k<64, false, false><<<cdiv(M, 8), 256>>>(bufA, off, srcs, dinv, nullptr, Bh, Bl, M);
    run_mm<64, false, true, true, true>(Bh, Bl, Whi + O_DW1, Wlo + O_DW1,
                                        db1, nullptr, Ahi, Alo, M, 256);

    // dec GCN2: t = h@dW2 -> fp32 ; A(t) -> split Bh/Bl [M,128]
    run_mm<256, false, false, false, false>(Ahi, Alo, Whi + O_DW2, Wlo + O_DW2,
                                            nullptr, bufA, nullptr, nullptr, M, 128);
    agg_k<128, false, false><<<cdiv(M, 8), 256>>>(bufA, off, srcs, dinv, nullptr, Bh, Bl, M);

    // out = a4@dWf + cb2
    run_mm<128, false, true, false, false>(Bh, Bl, Whi + O_DWF, Wlo + O_DWF,
                                           cbias + 1024, out, nullptr, nullptr, M, 1024);
}

// round 14
// speedup vs baseline: 1.0437x; 1.0010x over previous
#include <cuda_runtime.h>
#include <cuda_bf16.h>
#include <cstdint>

// ===========================================================================
// GCN auto-encoder.
//  - GEMMs: mma.sync m16n8k16 bf16 (HMMA), bf16x3 split (hi*hi+hi*lo+lo*hi,
//    fp32 accum) ~ fp32 accuracy. cp.async 2-stage pipeline + ldmatrix frags.
//    Pass order p0(ah*bh), p2(al*bh), p1(ah*bl) with cached bh frags:
//    8 ldmatrix.x4 per k-step instead of 10, same register peak.
//    BM=128, BN=64, 256 threads. AF32 variant converts fp32 A in-register.
//  - Aggregation: per-launch CSR, warp-per-node gather-reduce (unroll-8),
//    fused bias/relu/bf16-split epilogue. No float atomics.
//  - CSR build on forked stream; combine_bias ILP-4.
// ===========================================================================

constexpr int MAXN = 50000;
constexpr int MAXE = 800000;

__device__ __align__(256) float g_dinv[MAXN];
__device__ __align__(256) int   g_degi[MAXN];
__device__ __align__(256) int   g_off[MAXN + 1];
__device__ __align__(256) int   g_cur[MAXN];
__device__ __align__(256) int   g_srcs[MAXE];
__device__ __align__(256) float g_bufA[(size_t)MAXN * 128];
__device__ __align__(256) float g_cbias[2048];
__device__ __align__(256) __nv_bfloat16 g_Ahi[(size_t)MAXN * 256];
__device__ __align__(256) __nv_bfloat16 g_Alo[(size_t)MAXN * 256];
__device__ __align__(256) __nv_bfloat16 g_Bhi[(size_t)MAXN * 256];
__device__ __align__(256) __nv_bfloat16 g_Blo[(size_t)MAXN * 256];
__device__ __align__(256) __nv_bfloat16 g_Whi[262144];
__device__ __align__(256) __nv_bfloat16 g_Wlo[262144];

// ------------------------------- helpers -----------------------------------

__device__ __forceinline__ uint32_t smem_u32(const void* p) {
    uint32_t a;
    asm("{ .reg .u64 t; cvta.to.shared.u64 t, %1; cvt.u32.u64 %0, t; }"
        : "=r"(a) : "l"(p));
    return a;
}

__device__ __forceinline__ void cp16(uint32_t dst, const void* src, bool pred) {
    asm volatile("cp.async.cg.shared.global [%0], [%1], 16, %2;"
                 :: "r"(dst), "l"(src), "r"(pred ? 16 : 0));
}
__device__ __forceinline__ void cp_commit() {
    asm volatile("cp.async.commit_group;");
}
__device__ __forceinline__ void cp_wait1() {
    asm volatile("cp.async.wait_group 1;");
}

__device__ __forceinline__ void ldm_x4(uint32_t r[4], uint32_t addr) {
    asm volatile("ldmatrix.sync.aligned.m8n8.x4.shared.b16 {%0,%1,%2,%3}, [%4];"
                 : "=r"(r[0]), "=r"(r[1]), "=r"(r[2]), "=r"(r[3]) : "r"(addr));
}

__device__ __forceinline__ void mma16816(float c[4], const uint32_t a[4],
                                         const uint32_t b0, const uint32_t b1) {
    asm volatile(
        "mma.sync.aligned.m16n8k16.row.col.f32.bf16.bf16.f32 "
        "{%0,%1,%2,%3}, {%4,%5,%6,%7}, {%8,%9}, {%0,%1,%2,%3};"
        : "+f"(c[0]), "+f"(c[1]), "+f"(c[2]), "+f"(c[3])
        : "r"(a[0]), "r"(a[1]), "r"(a[2]), "r"(a[3]), "r"(b0), "r"(b1));
}

__device__ __forceinline__ uint32_t pack_bf162(__nv_bfloat16 a, __nv_bfloat16 b) {
    __nv_bfloat162 v = {a, b};
    return *(uint32_t*)&v;
}

// ------------------------------- tensor GEMM -------------------------------
// C[M,N] = A[M,K] @ W,  W pre-transposed+split to [N,K] bf16 hi/lo.
// BM=128, BN=64, BK=32, 256 threads (8 warps, 4Mx2N), 2-stage cp.async.
// AF32: A given as fp32; hi/lo fragments built in-register (split fused).

template <int K, bool AF32, bool BIAS, bool RELU, bool SPLITOUT>
__global__ void __launch_bounds__(256)
mm_k(const void* __restrict__ Apv, const __nv_bfloat16* __restrict__ Alo,
     const __nv_bfloat16* __restrict__ Bhi, const __nv_bfloat16* __restrict__ Blo,
     const float* __restrict__ bias, float* __restrict__ Cf,
     __nv_bfloat16* __restrict__ Chi, __nv_bfloat16* __restrict__ Clo,
     int M, int N) {
    constexpr int BM = 128, BK = 32, PITCH = 40;   // bf16 path: 80B rows
    constexpr int PITCHF = 40;                     // fp32 path: 160B rows
    constexpr int KT = K / BK;
    constexpr uint32_t BOFF_BYTES = 2 * 2 * 128 * PITCH * 2;   // 40960
    extern __shared__ char smem[];
    const uint32_t sbase = smem_u32(smem);
    const __nv_bfloat16* Ahi = (const __nv_bfloat16*)Apv;
    const float* Af = (const float*)Apv;
    float* smemF = (float*)smem;

    const int tid = threadIdx.x;
    const int lane = tid & 31, wid = tid >> 5;
    const int wm = wid & 3, wn = wid >> 2;
    const int bm = blockIdx.y * BM, bn = blockIdx.x * 64;

    float acc[2][4][4];
#pragma unroll
    for (int i = 0; i < 2; i++)
#pragma unroll
        for (int j = 0; j < 4; j++)
#pragma unroll
            for (int l = 0; l < 4; l++) acc[i][j][l] = 0.f;

    auto load_stage = [&](int st, int k0) {
        if (AF32) {
#pragma unroll
            for (int l = 0; l < 4; l++) {  // A fp32: 1024 16B chunks
                int idx = tid + l * 256;
                int row = idx >> 3, q = idx & 7;
                int g = bm + row;
                const float* src = Af + (size_t)g * K + k0 + q * 4;
                uint32_t dst = sbase +
                    (uint32_t)(((st * 128 + row) * PITCHF + q * 4) * 4);
                cp16(dst, src, g < M);
            }
        } else {
#pragma unroll
            for (int l = 0; l < 4; l++) {  // A bf16: 1024 16B chunks (2 mats)
                int idx = tid + l * 256;
                int mat = idx >> 9, rem = idx & 511, row = rem >> 2, q = rem & 3;
                int g = bm + row;
                const __nv_bfloat16* src =
                    (mat ? Alo : Ahi) + (size_t)g * K + k0 + q * 8;
                uint32_t dst = sbase +
                    (uint32_t)((((st * 2 + mat) * 128 + row) * PITCH + q * 8) * 2);
                cp16(dst, src, g < M);
            }
        }
#pragma unroll
        for (int l = 0; l < 2; l++) {  // B: 512 16B chunks
            int idx = tid + l * 256;
            int mat = idx >> 8, rem = idx & 255, row = rem >> 2, q = rem & 3;
            const __nv_bfloat16* src =
                (mat ? Blo : Bhi) + (size_t)(bn + row) * K + k0 + q * 8;
            uint32_t dst = sbase + BOFF_BYTES +
                (uint32_t)((((st * 2 + mat) * 64 + row) * PITCH + q * 8) * 2);
            cp16(dst, src, true);
        }
    };

    const int aRow = lane & 15, aCol = (lane >> 4) * 8;
    const int afRow = lane >> 2, afK = (lane & 3) * 2;
    const int bRow = ((lane >> 4) & 1) * 8 + (lane & 7);
    const int bCol = ((lane >> 3) & 1) * 8;

    load_stage(0, 0);
    cp_commit();

    for (int kt = 0; kt < KT; kt++) {
        if (kt + 1 < KT) load_stage((kt + 1) & 1, (kt + 1) * BK);
        cp_commit();
        cp_wait1();
        __syncthreads();

        const int st = kt & 1;
        const uint32_t bOff0 = BOFF_BYTES + (uint32_t)((st * 2) * 64 * PITCH) * 2;
        const uint32_t bOff1 = BOFF_BYTES + (uint32_t)((st * 2 + 1) * 64 * PITCH) * 2;

#pragma unroll
        for (int ks = 0; ks < 2; ks++) {
            const int kb = ks * 16;
            uint32_t afh[2][4], afl[2][4];

            if (AF32) {
                const int aBaseF = st * 128 * PITCHF;
#pragma unroll
                for (int mt = 0; mt < 2; mt++) {
                    int R = wm * 32 + mt * 16;
#pragma unroll
                    for (int i = 0; i < 4; i++) {
                        int rr = R + afRow + (i & 1) * 8;
                        int kk = kb + afK + (i >> 1) * 8;
                        float2 v = *(const float2*)(smemF + aBaseF + rr * PITCHF + kk);
                        __nv_bfloat16 h0 = __float2bfloat16(v.x);
                        __nv_bfloat16 h1 = __float2bfloat16(v.y);
                        afh[mt][i] = pack_bf162(h0, h1);
                        afl[mt][i] = pack_bf162(
                            __float2bfloat16(v.x - __bfloat162float(h0)),
                            __float2bfloat16(v.y - __bfloat162float(h1)));
                    }
                }
            } else {
                const uint32_t aOff0 = (uint32_t)((st * 2) * 128 * PITCH) * 2;
                const uint32_t aOff1 = (uint32_t)((st * 2 + 1) * 128 * PITCH) * 2;
#pragma unroll
                for (int mt = 0; mt < 2; mt++) {
                    int R = wm * 32 + mt * 16;
                    uint32_t rel = (uint32_t)((R + aRow) * PITCH + kb + aCol) * 2;
                    ldm_x4(afh[mt], sbase + aOff0 + rel);
                    ldm_x4(afl[mt], sbase + aOff1 + rel);
                }
            }

            // bh frags loaded once, reused for p0 (ah*bh) and p2 (al*bh)
            uint32_t bh[2][4];
#pragma unroll
            for (int pr = 0; pr < 2; pr++) {
                int R = wn * 32 + pr * 16;
                ldm_x4(bh[pr], sbase + bOff0 +
                       (uint32_t)((R + bRow) * PITCH + kb + bCol) * 2);
            }
#pragma unroll
            for (int mt = 0; mt < 2; mt++)
#pragma unroll
                for (int nt = 0; nt < 4; nt++)
                    mma16816(acc[mt][nt], afh[mt],
                             bh[nt >> 1][(nt & 1) * 2], bh[nt >> 1][(nt & 1) * 2 + 1]);
#pragma unroll
            for (int mt = 0; mt < 2; mt++)
#pragma unroll
                for (int nt = 0; nt < 4; nt++)
                    mma16816(acc[mt][nt], afl[mt],
                             bh[nt >> 1][(nt & 1) * 2], bh[nt >> 1][(nt & 1) * 2 + 1]);

            // bl pass: p1 (ah*bl)
            uint32_t bl[2][4];
#pragma unroll
            for (int pr = 0; pr < 2; pr++) {
                int R = wn * 32 + pr * 16;
                ldm_x4(bl[pr], sbase + bOff1 +
                       (uint32_t)((R + bRow) * PITCH + kb + bCol) * 2);
            }
#pragma unroll
            for (int mt = 0; mt < 2; mt++)
#pragma unroll
                for (int nt = 0; nt < 4; nt++)
                    mma16816(acc[mt][nt], afh[mt],
                             bl[nt >> 1][(nt & 1) * 2], bl[nt >> 1][(nt & 1) * 2 + 1]);
        }
        __syncthreads();
    }

    // epilogue
#pragma unroll
    for (int mt = 0; mt < 2; mt++) {
        int r0 = bm + wm * 32 + mt * 16 + (lane >> 2);
#pragma unroll
        for (int nt = 0; nt < 4; nt++) {
            int col = bn + wn * 32 + nt * 8 + (lane & 3) * 2;
            float b0 = 0.f, b1 = 0.f;
            if (BIAS) { b0 = __ldg(&bias[col]); b1 = __ldg(&bias[col + 1]); }
#pragma unroll
            for (int hh = 0; hh < 2; hh++) {
                int r = r0 + hh * 8;
                if (r < M) {
                    float v0 = acc[mt][nt][hh * 2 + 0] + b0;
                    float v1 = acc[mt][nt][hh * 2 + 1] + b1;
                    if (RELU) { v0 = fmaxf(v0, 0.f); v1 = fmaxf(v1, 0.f); }
                    if (SPLITOUT) {
                        __nv_bfloat16 h0 = __float2bfloat16(v0);
                        __nv_bfloat16 h1 = __float2bfloat16(v1);
                        __nv_bfloat162 hv = {h0, h1};
                        __nv_bfloat162 lv = {
                            __float2bfloat16(v0 - __bfloat162float(h0)),
                            __float2bfloat16(v1 - __bfloat162float(h1))};
                        *(__nv_bfloat162*)(Chi + (size_t)r * N + col) = hv;
                        *(__nv_bfloat162*)(Clo + (size_t)r * N + col) = lv;
                    } else {
                        *(float2*)(Cf + (size_t)r * N + col) = make_float2(v0, v1);
                    }
                }
            }
        }
    }
}

// ------------------------------ CSR building -------------------------------

__global__ void deg_count_k(const int* __restrict__ dst, int* d, int E) {
    int e = blockIdx.x * blockDim.x + threadIdx.x;
    if (e < E) atomicAdd(&d[dst[e]], 1);
}

__global__ void scan_k(const int* __restrict__ deg, int* __restrict__ off,
                       int* __restrict__ cur, float* __restrict__ dinv, int n) {
    __shared__ int part[1024];
    int t = threadIdx.x;
    int per = (n + 1023) >> 10;
    int lo = t * per;
    int hi = min(lo + per, n);
    int s = 0;
    for (int i = lo; i < hi; i++) s += deg[i];
    part[t] = s;
    __syncthreads();
    for (int d = 1; d < 1024; d <<= 1) {
        int v = (t >= d) ? part[t - d] : 0;
        __syncthreads();
        part[t] += v;
        __syncthreads();
    }
    int run = (t == 0) ? 0 : part[t - 1];
    for (int i = lo; i < hi; i++) {
        off[i] = run;
        cur[i] = run;
        dinv[i] = rsqrtf((float)(deg[i] + 1));
        run += deg[i];
    }
    if (t == 1023) off[n] = part[1023];
}

__global__ void fill_k(const int* __restrict__ src, const int* __restrict__ dst,
                       int* cur, int* __restrict__ srcs, int E) {
    int e = blockIdx.x * blockDim.x + threadIdx.x;
    if (e < E) {
        int p = atomicAdd(&cur[dst[e]], 1);
        srcs[p] = src[e];
    }
}

// ------------------------------ aggregation --------------------------------

template <int C, bool BIAS, bool RELU>
__global__ void __launch_bounds__(256)
agg_k(const float* __restrict__ h, const int* __restrict__ off,
      const int* __restrict__ srcs, const float* __restrict__ dinv,
      const float* __restrict__ bias,
      __nv_bfloat16* __restrict__ Hi, __nv_bfloat16* __restrict__ Lo, int n) {
    constexpr int V = C / 32;
    int node = blockIdx.x * 8 + (threadIdx.x >> 5);
    if (node >= n) return;
    int lane = threadIdx.x & 31;
    int c = lane * V;
    float dv = dinv[node];

    float acc[V];
    {
        if (V == 4) {
            float4 v = *(const float4*)(h + (size_t)node * C + c);
            acc[0] = dv * v.x; acc[1] = dv * v.y;
            acc[2] = dv * v.z; acc[3] = dv * v.w;
        } else {
            float2 v = *(const float2*)(h + (size_t)node * C + c);
            acc[0] = dv * v.x; acc[1] = dv * v.y;
        }
    }

    const int b = off[node], e = off[node + 1];
    int i0 = b;
    for (; i0 + 32 <= e; i0 += 32) {
        int s = __ldg(&srcs[i0 + lane]);
        float nd = __ldg(&dinv[s]);
#pragma unroll 8
        for (int j = 0; j < 32; j++) {
            int ss = __shfl_sync(0xffffffffu, s, j);
            float nn = __shfl_sync(0xffffffffu, nd, j);
            const float* p = h + (size_t)ss * C + c;
            if (V == 4) {
                float4 v = *(const float4*)p;
                acc[0] = fmaf(nn, v.x, acc[0]);
                acc[1] = fmaf(nn, v.y, acc[1]);
                acc[2] = fmaf(nn, v.z, acc[2]);
                acc[3] = fmaf(nn, v.w, acc[3]);
            } else {
                float2 v = *(const float2*)p;
                acc[0] = fmaf(nn, v.x, acc[0]);
                acc[1] = fmaf(nn, v.y, acc[1]);
            }
        }
    }
    if (i0 < e) {
        int idx = i0 + lane;
        int s = 0;
        float nd = 0.f;
        if (idx < e) {
            s = __ldg(&srcs[idx]);
            nd = __ldg(&dinv[s]);
        }
        int cnt = e - i0;
#pragma unroll 4
        for (int j = 0; j < cnt; j++) {
            int ss = __shfl_sync(0xffffffffu, s, j);
            float nn = __shfl_sync(0xffffffffu, nd, j);
            const float* p = h + (size_t)ss * C + c;
            if (V == 4) {
                float4 v = *(const float4*)p;
                acc[0] = fmaf(nn, v.x, acc[0]);
                acc[1] = fmaf(nn, v.y, acc[1]);
                acc[2] = fmaf(nn, v.z, acc[2]);
                acc[3] = fmaf(nn, v.w, acc[3]);
            } else {
                float2 v = *(const float2*)p;
                acc[0] = fmaf(nn, v.x, acc[0]);
                acc[1] = fmaf(nn, v.y, acc[1]);
            }
        }
    }

#pragma unroll
    for (int k = 0; k < V; k++) {
        acc[k] *= dv;
        if (BIAS) acc[k] += __ldg(&bias[c + k]);
        if (RELU) acc[k] = fmaxf(acc[k], 0.f);
    }
#pragma unroll
    for (int k = 0; k < V; k += 2) {
        __nv_bfloat16 h0 = __float2bfloat16(acc[k]);
        __nv_bfloat16 h1 = __float2bfloat16(acc[k + 1]);
        __nv_bfloat162 hv = {h0, h1};
        __nv_bfloat162 lv = {__float2bfloat16(acc[k] - __bfloat162float(h0)),
                             __float2bfloat16(acc[k + 1] - __bfloat162float(h1))};
        *(__nv_bfloat162*)(Hi + (size_t)node * C + c + k) = hv;
        *(__nv_bfloat162*)(Lo + (size_t)node * C + c + k) = lv;
    }
}

// ------------------------------ split / misc -------------------------------

struct WJobs {
    const float* W[6];
    int K[6], N[6], off[6], elems[6];
};

__global__ void wsplit_all_k(WJobs P, __nv_bfloat16* __restrict__ hi,
                             __nv_bfloat16* __restrict__ lo) {
    int i = blockIdx.x * blockDim.x + threadIdx.x;
#pragma unroll
    for (int j = 0; j < 6; j++) {
        if (i < P.elems[j]) {
            int K = P.K[j], N = P.N[j];
            int n = i / K, k = i % K;
            float v = P.W[j][(long)k * N + n];
            __nv_bfloat16 h = __float2bfloat16(v);
            hi[P.off[j] + i] = h;
            lo[P.off[j] + i] = __float2bfloat16(v - __bfloat162float(h));
            return;
        }
        i -= P.elems[j];
    }
}

__global__ void combine_bias_k(const float* __restrict__ b1, const float* __restrict__ W,
                               const float* __restrict__ b2, float* __restrict__ cb,
                               int K, int N) {
    int j = blockIdx.x * blockDim.x + threadIdx.x;
    if (j >= N) return;
    float s0 = 0.f, s1 = 0.f, s2 = 0.f, s3 = 0.f;
    for (int k = 0; k < K; k += 4) {
        s0 = fmaf(b1[k + 0], W[(long)(k + 0) * N + j], s0);
        s1 = fmaf(b1[k + 1], W[(long)(k + 1) * N + j], s1);
        s2 = fmaf(b1[k + 2], W[(long)(k + 2) * N + j], s2);
        s3 = fmaf(b1[k + 3], W[(long)(k + 3) * N + j], s3);
    }
    cb[j] = (s0 + s1) + (s2 + s3) + b2[j];
}

// --------------------------------- launch ----------------------------------

static inline int cdiv(long a, long b) { return (int)((a + b - 1) / b); }

constexpr int MM_SMEM = (2 * 2 * 128 * 40 + 2 * 2 * 64 * 40) * 2;  // 61440B

template <int K, bool AF32, bool BIAS, bool RELU, bool SPLITOUT>
static void run_mm(const void* A, const __nv_bfloat16* Alo,
                   const __nv_bfloat16* Bhi, const __nv_bfloat16* Blo,
                   const float* bias, float* Cf, __nv_bfloat16* Chi,
                   __nv_bfloat16* Clo, int M, int N) {
    cudaFuncSetAttribute(mm_k<K, AF32, BIAS, RELU, SPLITOUT>,
                         cudaFuncAttributeMaxDynamicSharedMemorySize, MM_SMEM);
    dim3 g(N / 64, cdiv(M, 128));
    mm_k<K, AF32, BIAS, RELU, SPLITOUT><<<g, 256, MM_SMEM>>>(
        A, Alo, Bhi, Blo, bias, Cf, Chi, Clo, M, N);
}

extern "C" void kernel_launch(void* const* d_in, const int* in_sizes, int n_in,
                              void* d_out, int out_size) {
    const float* x   = (const float*)d_in[0];
    const int*   ei  = (const int*)d_in[1];
    const float* eW1 = (const float*)d_in[2];
    const float* eb1 = (const float*)d_in[3];
    const float* eW2 = (const float*)d_in[4];
    const float* eb2 = (const float*)d_in[5];
    const float* eWf = (const float*)d_in[6];
    const float* ebf = (const float*)d_in[7];
    const float* dW1 = (const float*)d_in[8];
    const float* db1 = (const float*)d_in[9];
    const float* dW2 = (const float*)d_in[10];
    const float* db2 = (const float*)d_in[11];
    const float* dWf = (const float*)d_in[12];
    const float* dbf = (const float*)d_in[13];
    float* out = (float*)d_out;

    const int M = in_sizes[0] / 128;  // 50000
    const int E = in_sizes[1] / 2;    // 800000
    const int* src = ei;
    const int* dst = ei + E;

    float *dinv, *bufA, *cbias;
    int *degi, *off, *cur, *srcs;
    __nv_bfloat16 *Ahi, *Alo, *Bh, *Bl, *Whi, *Wlo;
    cudaGetSymbolAddress((void**)&dinv, g_dinv);
    cudaGetSymbolAddress((void**)&degi, g_degi);
    cudaGetSymbolAddress((void**)&off, g_off);
    cudaGetSymbolAddress((void**)&cur, g_cur);
    cudaGetSymbolAddress((void**)&srcs, g_srcs);
    cudaGetSymbolAddress((void**)&bufA, g_bufA);
    cudaGetSymbolAddress((void**)&cbias, g_cbias);
    cudaGetSymbolAddress((void**)&Ahi, g_Ahi);
    cudaGetSymbolAddress((void**)&Alo, g_Alo);
    cudaGetSymbolAddress((void**)&Bh, g_Bhi);
    cudaGetSymbolAddress((void**)&Bl, g_Blo);
    cudaGetSymbolAddress((void**)&Whi, g_Whi);
    cudaGetSymbolAddress((void**)&Wlo, g_Wlo);

    const int O_EW1 = 0;      // 128x128
    const int O_EW2 = 16384;  // 64x128
    const int O_EWF = 24576;  // 64x64
    const int O_DW1 = 28672;  // 256x64
    const int O_DW2 = 45056;  // 128x256
    const int O_DWF = 77824;  // 1024x128

    const int T = 256;

    static cudaStream_t s2 = nullptr;
    static cudaEvent_t evFork = nullptr, evJoin = nullptr;
    if (!s2) {
        cudaStreamCreateWithFlags(&s2, cudaStreamNonBlocking);
        cudaEventCreateWithFlags(&evFork, cudaEventDisableTiming);
        cudaEventCreateWithFlags(&evJoin, cudaEventDisableTiming);
    }

    // ---- fork: CSR build on s2 ----
    cudaEventRecord(evFork, 0);
    cudaStreamWaitEvent(s2, evFork, 0);
    cudaMemsetAsync(degi, 0, M * sizeof(int), s2);
    deg_count_k<<<cdiv(E, T), T, 0, s2>>>(dst, degi, E);
    scan_k<<<1, 1024, 0, s2>>>(degi, off, cur, dinv, M);
    fill_k<<<cdiv(E, T), T, 0, s2>>>(src, dst, cur, srcs, E);
    cudaEventRecord(evJoin, s2);

    // ---- main stream: weight prep + combined biases + first GEMM ----
    {
        WJobs P;
        const float* Ws[6] = {eW1, eW2, eWf, dW1, dW2, dWf};
        int Ks[6] = {128, 128, 64, 64, 256, 128};
        int Ns[6] = {128, 64, 64, 256, 128, 1024};
        int Os[6] = {O_EW1, O_EW2, O_EWF, O_DW1, O_DW2, O_DWF};
        int total = 0;
        for (int j = 0; j < 6; j++) {
            P.W[j] = Ws[j]; P.K[j] = Ks[j]; P.N[j] = Ns[j];
            P.off[j] = Os[j]; P.elems[j] = Ks[j] * Ns[j];
            total += P.elems[j];
        }
        wsplit_all_k<<<cdiv(total, T), T>>>(P, Whi, Wlo);
    }
    combine_bias_k<<<1, 64>>>(eb2, eWf, ebf, cbias, 64, 64);
    combine_bias_k<<<cdiv(1024, 128), 128>>>(db2, dWf, dbf, cbias + 1024, 128, 1024);

    // enc GCN1 linear part: t1 = x@eW1 (fp32 A, split fused in-kernel)
    run_mm<128, true, false, false, false>(x, nullptr, Whi + O_EW1, Wlo + O_EW1,
                                           nullptr, bufA, nullptr, nullptr, M, 128);

    // ---- join: aggregation needs CSR ----
    cudaStreamWaitEvent(0, evJoin, 0);

    // h1 = relu(A(t1)+eb1) -> split Bh/Bl [M,128]
    agg_k<128, true, true><<<cdiv(M, 8), 256>>>(bufA, off, srcs, dinv, eb1, Bh, Bl, M);

    // enc GCN2: t2 = h1@eW2 ; A(t2) -> split Ahi/Alo [M,64]
    run_mm<128, false, false, false, false>(Bh, Bl, Whi + O_EW2, Wlo + O_EW2,
                                            nullptr, bufA, nullptr, nullptr, M, 64);
    agg_k<64, false, false><<<cdiv(M, 8), 256>>>(bufA, off, srcs, dinv, nullptr, Ahi, Alo, M);

    // z = a2@eWf + cb -> fp32 bufA [M,64]
    run_mm<64, false, true, false, false>(Ahi, Alo, Whi + O_EWF, Wlo + O_EWF,
                                          cbias, bufA, nullptr, nullptr, M, 64);

    // dec GCN1: A(z) -> split Bh/Bl ; h = relu(A(z)@dW1+db1) -> split Ahi/Alo [M,256]
    agg_k<64, false, false><<<cdiv(M, 8), 256>>>(bufA, off, srcs, dinv, nullptr, Bh, Bl, M);
    run_mm<64, false, true, true, true>(Bh, Bl, Whi + O_DW1, Wlo + O_DW1,
                                        db1, nullptr, Ahi, Alo, M, 256);

    // dec GCN2: t = h@dW2 -> fp32 ; A(t) -> split Bh/Bl [M,128]
    run_mm<256, false, false, false, false>(Ahi, Alo, Whi + O_DW2, Wlo + O_DW2,
                                            nullptr, bufA, nullptr, nullptr, M, 128);
    agg_k<128, false, false><<<cdiv(M, 8), 256>>>(bufA, off, srcs, dinv, nullptr, Bh, Bl, M);

    // out = a4@dWf + cb2
    run_mm<128, false, true, false, false>(Bh, Bl, Whi + O_DWF, Wlo + O_DWF,
                                           cbias + 1024, out, nullptr, nullptr, M, 1024);
}